// round 11
// baseline (speedup 1.0000x reference)
#include <cuda_runtime.h>
#include <cuda_fp16.h>
#include <math.h>
#include <stdint.h>

#define NNODES 100000
#define NEDGES 1600000

// packed f32x2 FMA: d = a*b + d (elementwise on 2 packed fp32)
#define FMA2(d, a, b) \
    asm("fma.rn.f32x2 %0, %1, %2, %0;" : "+l"(d) : "l"(a), "l"(b))

__device__ __forceinline__ float f2lo(unsigned long long v) {
    return __uint_as_float((unsigned)(v & 0xffffffffull));
}
__device__ __forceinline__ float f2hi(unsigned long long v) {
    return __uint_as_float((unsigned)(v >> 32));
}
__device__ __forceinline__ unsigned long long packf2(float lo, float hi) {
    return (unsigned long long)__float_as_uint(lo) |
           ((unsigned long long)__float_as_uint(hi) << 32);
}
__device__ __forceinline__ float lrelu(float x) {
    return x > 0.f ? x : 0.2f * x;
}

// ---------------- scratch (device globals) ----------------
__device__ __align__(128) __half g_hh0[NNODES * 128];  // layer-0 H (fp16)
__device__ __align__(128) __half g_hh1[NNODES * 128];  // layer-1 H (fp16)
__device__ __align__(128) __half g_h2[NNODES * 32];    // layer-2 H (fp16)
__device__ __align__(128) ulonglong2 g_Wp0[4096];      // prepacked W0 (64KB)
__device__ __align__(128) ulonglong2 g_Wp1[4096];      // prepacked W1 (64KB)
__device__ float g_als0[NNODES * 4];
__device__ float g_ald0[NNODES * 4];
__device__ float g_als1[NNODES * 4];
__device__ float g_ald1[NNODES * 4];
__device__ float g_als2[NNODES];
__device__ float g_ald2[NNODES];
__device__ int   g_deg[NNODES];
__device__ int   g_off[NNODES + 1];
__device__ int   g_cur[NNODES];
__device__ int   g_bsum[128];
__device__ int   g_csr[NEDGES];

// ---------------- CSR build ----------------
__global__ void zero_deg_kernel(int n) {
    int i = blockIdx.x * blockDim.x + threadIdx.x;
    if (i < n) g_deg[i] = 0;
}
__global__ void count_kernel(const int* __restrict__ ei, int e) {
    int i = blockIdx.x * blockDim.x + threadIdx.x;
    if (i < e) atomicAdd(&g_deg[ei[e + i]], 1);
}
__global__ void scan1_kernel(int n) {
    __shared__ int sm[1024];
    int i = blockIdx.x * 1024 + threadIdx.x;
    int v = (i < n) ? g_deg[i] : 0;
    sm[threadIdx.x] = v;
    __syncthreads();
    #pragma unroll
    for (int d = 1; d < 1024; d <<= 1) {
        int t = (threadIdx.x >= d) ? sm[threadIdx.x - d] : 0;
        __syncthreads();
        sm[threadIdx.x] += t;
        __syncthreads();
    }
    if (i < n) g_off[i] = sm[threadIdx.x] - v;
    if (threadIdx.x == 1023) g_bsum[blockIdx.x] = sm[1023];
}
__global__ void scan2_kernel(int nb) {
    __shared__ int sm[128];
    int t = threadIdx.x;
    int v = (t < nb) ? g_bsum[t] : 0;
    sm[t] = v;
    __syncthreads();
    #pragma unroll
    for (int d = 1; d < 128; d <<= 1) {
        int tv = (t >= d) ? sm[t - d] : 0;
        __syncthreads();
        sm[t] += tv;
        __syncthreads();
    }
    if (t < nb) g_bsum[t] = sm[t] - v;
}
__global__ void scan3_kernel(int n, int e) {
    int i = blockIdx.x * 1024 + threadIdx.x;
    if (i < n) {
        int o = g_off[i] + g_bsum[blockIdx.x];
        g_off[i] = o;
        g_cur[i] = o;
    }
    if (i == 0) g_off[n] = e;
}
__global__ void fill_kernel(const int* __restrict__ ei, int e) {
    int i = blockIdx.x * blockDim.x + threadIdx.x;
    if (i < e) {
        int src = ei[i];
        int dst = ei[e + i];
        int pos = atomicAdd(&g_cur[dst], 1);
        g_csr[pos] = src;
    }
}

// ---------------- W prepack: Wp[(k2*2+half)*32 + l] for the 128-col GEMMs ----------
__global__ void packW128_kernel(const float* __restrict__ W, ulonglong2* __restrict__ Wp) {
    int i = blockIdx.x * 256 + threadIdx.x;   // < 4096
    int k2 = i >> 6;
    int half_ = (i >> 5) & 1;
    int l = i & 31;
    int c0 = 2 * l + 64 * half_;
    ulonglong2 p;
    p.x = packf2(W[(2 * k2) * 128 + c0], W[(2 * k2 + 1) * 128 + c0]);
    p.y = packf2(W[(2 * k2) * 128 + c0 + 1], W[(2 * k2 + 1) * 128 + c0 + 1]);
    Wp[i] = p;
}

// ---------------- per-node aggregation helper (4 heads x 32ch, fp16 H) ------------
// Returns softmax-weighted mean (float4, lane owns channels 4L..4L+3).
__device__ __forceinline__ float4 agg_node128(
    const uint2* __restrict__ Hh, const float* __restrict__ als,
    float aldv, int head, int lane, int s0, int s1)
{
    float s = 0.f;
    float4 acc = make_float4(0.f, 0.f, 0.f, 0.f);
    int idx = s0;
    for (; idx + 4 <= s1; idx += 4) {
        int u0 = __ldg(&g_csr[idx]);
        int u1 = __ldg(&g_csr[idx + 1]);
        int u2 = __ldg(&g_csr[idx + 2]);
        int u3 = __ldg(&g_csr[idx + 3]);
        float e0 = __ldg(&als[u0 * 4 + head]) + aldv;
        float e1 = __ldg(&als[u1 * 4 + head]) + aldv;
        float e2 = __ldg(&als[u2 * 4 + head]) + aldv;
        float e3 = __ldg(&als[u3 * 4 + head]) + aldv;
        uint2 p0 = __ldg(&Hh[(size_t)u0 * 32 + lane]);
        uint2 p1 = __ldg(&Hh[(size_t)u1 * 32 + lane]);
        uint2 p2 = __ldg(&Hh[(size_t)u2 * 32 + lane]);
        uint2 p3 = __ldg(&Hh[(size_t)u3 * 32 + lane]);
        float w0 = __expf(lrelu(e0));
        float w1 = __expf(lrelu(e1));
        float w2 = __expf(lrelu(e2));
        float w3 = __expf(lrelu(e3));
        s += (w0 + w1) + (w2 + w3);
        float2 a0 = __half22float2(*(__half2*)&p0.x), b0 = __half22float2(*(__half2*)&p0.y);
        float2 a1 = __half22float2(*(__half2*)&p1.x), b1 = __half22float2(*(__half2*)&p1.y);
        float2 a2 = __half22float2(*(__half2*)&p2.x), b2 = __half22float2(*(__half2*)&p2.y);
        float2 a3 = __half22float2(*(__half2*)&p3.x), b3 = __half22float2(*(__half2*)&p3.y);
        acc.x += w0 * a0.x + w1 * a1.x + w2 * a2.x + w3 * a3.x;
        acc.y += w0 * a0.y + w1 * a1.y + w2 * a2.y + w3 * a3.y;
        acc.z += w0 * b0.x + w1 * b1.x + w2 * b2.x + w3 * b3.x;
        acc.w += w0 * b0.y + w1 * b1.y + w2 * b2.y + w3 * b3.y;
    }
    for (; idx < s1; idx++) {
        int u = __ldg(&g_csr[idx]);
        float wt = __expf(lrelu(__ldg(&als[u * 4 + head]) + aldv));
        uint2 p = __ldg(&Hh[(size_t)u * 32 + lane]);
        float2 a = __half22float2(*(__half2*)&p.x), b = __half22float2(*(__half2*)&p.y);
        s += wt;
        acc.x += wt * a.x;
        acc.y += wt * a.y;
        acc.z += wt * b.x;
        acc.w += wt * b.y;
    }
    float inv = 1.f / (s + 1e-16f);
    acc.x *= inv; acc.y *= inv; acc.z *= inv; acc.w *= inv;
    return acc;
}

// ---------------- K1: GEMM 128->128 (x @ W0) + fused logits ----------------
__global__ __launch_bounds__(256, 3) void gemm128_kernel(
    const float4* __restrict__ A4, const ulonglong2* __restrict__ Wp,
    const float* __restrict__ asrc, const float* __restrict__ adst,
    __half2* __restrict__ Hh, float* __restrict__ als, float* __restrict__ ald, int n)
{
    __shared__ float4 Asm4[1024];
    int tid = threadIdx.x;
    int rowbase = blockIdx.x * 32;
    #pragma unroll
    for (int i = tid; i < 1024; i += 256) {
        int row = rowbase + (i >> 5);
        Asm4[i] = (row < n) ? A4[(size_t)row * 32 + (i & 31)]
                            : make_float4(0.f, 0.f, 0.f, 0.f);
    }
    __syncthreads();

    int w = tid >> 5, lane = tid & 31;
    unsigned long long acc[4][4];
    #pragma unroll
    for (int r = 0; r < 4; r++)
        #pragma unroll
        for (int c = 0; c < 4; c++) acc[r][c] = 0ull;

    #pragma unroll 4
    for (int k4 = 0; k4 < 32; k4++) {
        ulonglong2 wa0 = __ldg(&Wp[((2 * k4) * 2 + 0) * 32 + lane]);
        ulonglong2 wb0 = __ldg(&Wp[((2 * k4) * 2 + 1) * 32 + lane]);
        ulonglong2 wa1 = __ldg(&Wp[((2 * k4 + 1) * 2 + 0) * 32 + lane]);
        ulonglong2 wb1 = __ldg(&Wp[((2 * k4 + 1) * 2 + 1) * 32 + lane]);
        #pragma unroll
        for (int r = 0; r < 4; r++) {
            ulonglong2 ap = *(const ulonglong2*)&Asm4[(w * 4 + r) * 32 + k4];
            FMA2(acc[r][0], ap.x, wa0.x);
            FMA2(acc[r][1], ap.x, wa0.y);
            FMA2(acc[r][2], ap.x, wb0.x);
            FMA2(acc[r][3], ap.x, wb0.y);
            FMA2(acc[r][0], ap.y, wa1.x);
            FMA2(acc[r][1], ap.y, wa1.y);
            FMA2(acc[r][2], ap.y, wb1.x);
            FMA2(acc[r][3], ap.y, wb1.y);
        }
    }

    int c0 = 2 * lane;
    float as0 = asrc[c0], as1 = asrc[c0 + 1], as2_ = asrc[c0 + 64], as3 = asrc[c0 + 65];
    float ad0 = adst[c0], ad1 = adst[c0 + 1], ad2_ = adst[c0 + 64], ad3 = adst[c0 + 65];
    int hA = lane >> 4;
    #pragma unroll
    for (int r = 0; r < 4; r++) {
        int row = rowbase + w * 4 + r;
        if (row >= n) break;
        float v0 = f2lo(acc[r][0]) + f2hi(acc[r][0]);
        float v1 = f2lo(acc[r][1]) + f2hi(acc[r][1]);
        float v2 = f2lo(acc[r][2]) + f2hi(acc[r][2]);
        float v3 = f2lo(acc[r][3]) + f2hi(acc[r][3]);
        Hh[(size_t)row * 64 + lane] = __floats2half2_rn(v0, v1);
        Hh[(size_t)row * 64 + 32 + lane] = __floats2half2_rn(v2, v3);
        float psl = v0 * as0 + v1 * as1;
        float psh = v2 * as2_ + v3 * as3;
        float pdl = v0 * ad0 + v1 * ad1;
        float pdh = v2 * ad2_ + v3 * ad3;
        #pragma unroll
        for (int o = 1; o < 16; o <<= 1) {
            psl += __shfl_xor_sync(0xffffffffu, psl, o);
            psh += __shfl_xor_sync(0xffffffffu, psh, o);
            pdl += __shfl_xor_sync(0xffffffffu, pdl, o);
            pdh += __shfl_xor_sync(0xffffffffu, pdh, o);
        }
        if ((lane & 15) == 0) {
            als[row * 4 + hA] = psl;
            als[row * 4 + hA + 2] = psh;
            ald[row * 4 + hA] = pdl;
            ald[row * 4 + hA + 2] = pdh;
        }
    }
}

// ---------------- K2: fused agg128 + BN + ELU + GEMM 128->128 + logits --------------
// Block owns 32 nodes. Warp w aggregates nodes w*4..w*4+3 into smem (feat never
// touches gmem), then the 32x128 @ 128x128 GEMM runs from smem.
__global__ __launch_bounds__(256) void fused_agg_gemm128_kernel(
    const uint2* __restrict__ Hh_in, const float* __restrict__ als_in,
    const float* __restrict__ ald_in,
    const float* __restrict__ bias, const float* __restrict__ gamma,
    const float* __restrict__ beta, const float* __restrict__ mean,
    const float* __restrict__ var,
    const ulonglong2* __restrict__ Wp,
    const float* __restrict__ asrc, const float* __restrict__ adst,
    __half2* __restrict__ Hh_out, float* __restrict__ als_out,
    float* __restrict__ ald_out, int n)
{
    __shared__ float4 Asm4[1024];   // 32 rows x 128 ch fp32 = 16KB
    int tid = threadIdx.x;
    int w = tid >> 5, lane = tid & 31, head = lane >> 3;
    int rowbase = blockIdx.x * 32;

    float4 bi = ((const float4*)bias)[lane];
    float4 mn = ((const float4*)mean)[lane];
    float4 vr = ((const float4*)var)[lane];
    float4 gm = ((const float4*)gamma)[lane];
    float4 bt = ((const float4*)beta)[lane];
    float rsx = rsqrtf(vr.x + 1e-5f), rsy = rsqrtf(vr.y + 1e-5f);
    float rsz = rsqrtf(vr.z + 1e-5f), rsw = rsqrtf(vr.w + 1e-5f);

    #pragma unroll
    for (int r = 0; r < 4; r++) {
        int v = rowbase + w * 4 + r;
        float4 y = make_float4(0.f, 0.f, 0.f, 0.f);
        if (v < n) {
            float aldv = __ldg(&ald_in[v * 4 + head]);
            float4 a = agg_node128(Hh_in, als_in, aldv, head, lane,
                                   g_off[v], g_off[v + 1]);
            y.x = (a.x + bi.x - mn.x) * rsx * gm.x + bt.x;
            y.y = (a.y + bi.y - mn.y) * rsy * gm.y + bt.y;
            y.z = (a.z + bi.z - mn.z) * rsz * gm.z + bt.z;
            y.w = (a.w + bi.w - mn.w) * rsw * gm.w + bt.w;
            y.x = y.x > 0.f ? y.x : expm1f(y.x);
            y.y = y.y > 0.f ? y.y : expm1f(y.y);
            y.z = y.z > 0.f ? y.z : expm1f(y.z);
            y.w = y.w > 0.f ? y.w : expm1f(y.w);
        }
        Asm4[(w * 4 + r) * 32 + lane] = y;
    }
    __syncthreads();

    unsigned long long acc[4][4];
    #pragma unroll
    for (int r = 0; r < 4; r++)
        #pragma unroll
        for (int c = 0; c < 4; c++) acc[r][c] = 0ull;

    #pragma unroll 4
    for (int k4 = 0; k4 < 32; k4++) {
        ulonglong2 wa0 = __ldg(&Wp[((2 * k4) * 2 + 0) * 32 + lane]);
        ulonglong2 wb0 = __ldg(&Wp[((2 * k4) * 2 + 1) * 32 + lane]);
        ulonglong2 wa1 = __ldg(&Wp[((2 * k4 + 1) * 2 + 0) * 32 + lane]);
        ulonglong2 wb1 = __ldg(&Wp[((2 * k4 + 1) * 2 + 1) * 32 + lane]);
        #pragma unroll
        for (int r = 0; r < 4; r++) {
            ulonglong2 ap = *(const ulonglong2*)&Asm4[(w * 4 + r) * 32 + k4];
            FMA2(acc[r][0], ap.x, wa0.x);
            FMA2(acc[r][1], ap.x, wa0.y);
            FMA2(acc[r][2], ap.x, wb0.x);
            FMA2(acc[r][3], ap.x, wb0.y);
            FMA2(acc[r][0], ap.y, wa1.x);
            FMA2(acc[r][1], ap.y, wa1.y);
            FMA2(acc[r][2], ap.y, wb1.x);
            FMA2(acc[r][3], ap.y, wb1.y);
        }
    }

    int c0 = 2 * lane;
    float as0 = asrc[c0], as1 = asrc[c0 + 1], as2_ = asrc[c0 + 64], as3 = asrc[c0 + 65];
    float ad0 = adst[c0], ad1 = adst[c0 + 1], ad2_ = adst[c0 + 64], ad3 = adst[c0 + 65];
    int hA = lane >> 4;
    #pragma unroll
    for (int r = 0; r < 4; r++) {
        int row = rowbase + w * 4 + r;
        if (row >= n) break;
        float v0 = f2lo(acc[r][0]) + f2hi(acc[r][0]);
        float v1 = f2lo(acc[r][1]) + f2hi(acc[r][1]);
        float v2 = f2lo(acc[r][2]) + f2hi(acc[r][2]);
        float v3 = f2lo(acc[r][3]) + f2hi(acc[r][3]);
        Hh_out[(size_t)row * 64 + lane] = __floats2half2_rn(v0, v1);
        Hh_out[(size_t)row * 64 + 32 + lane] = __floats2half2_rn(v2, v3);
        float psl = v0 * as0 + v1 * as1;
        float psh = v2 * as2_ + v3 * as3;
        float pdl = v0 * ad0 + v1 * ad1;
        float pdh = v2 * ad2_ + v3 * ad3;
        #pragma unroll
        for (int o = 1; o < 16; o <<= 1) {
            psl += __shfl_xor_sync(0xffffffffu, psl, o);
            psh += __shfl_xor_sync(0xffffffffu, psh, o);
            pdl += __shfl_xor_sync(0xffffffffu, pdl, o);
            pdh += __shfl_xor_sync(0xffffffffu, pdh, o);
        }
        if ((lane & 15) == 0) {
            als_out[row * 4 + hA] = psl;
            als_out[row * 4 + hA + 2] = psh;
            ald_out[row * 4 + hA] = pdl;
            ald_out[row * 4 + hA + 2] = pdh;
        }
    }
}

// ---------------- K3: fused agg128 + BN + ELU + GEMM 128->32 + logits ---------------
__global__ __launch_bounds__(256) void fused_agg_gemm32_kernel(
    const uint2* __restrict__ Hh_in, const float* __restrict__ als_in,
    const float* __restrict__ ald_in,
    const float* __restrict__ bias, const float* __restrict__ gamma,
    const float* __restrict__ beta, const float* __restrict__ mean,
    const float* __restrict__ var,
    const float* __restrict__ W2,
    const float* __restrict__ asrc, const float* __restrict__ adst,
    __half* __restrict__ Hh_out, float* __restrict__ als_out,
    float* __restrict__ ald_out, int n)
{
    __shared__ float4 Asm4[1024];               // 16KB
    __shared__ unsigned long long Wp2s[2048];   // 16KB
    int tid = threadIdx.x;
    int w = tid >> 5, lane = tid & 31, head = lane >> 3;
    int rowbase = blockIdx.x * 32;

    #pragma unroll 2
    for (int i = tid; i < 2048; i += 256) {
        int k2 = i >> 5, l = i & 31;
        Wp2s[i] = packf2(W2[(k2 * 2) * 32 + l], W2[(k2 * 2 + 1) * 32 + l]);
    }

    float4 bi = ((const float4*)bias)[lane];
    float4 mn = ((const float4*)mean)[lane];
    float4 vr = ((const float4*)var)[lane];
    float4 gm = ((const float4*)gamma)[lane];
    float4 bt = ((const float4*)beta)[lane];
    float rsx = rsqrtf(vr.x + 1e-5f), rsy = rsqrtf(vr.y + 1e-5f);
    float rsz = rsqrtf(vr.z + 1e-5f), rsw = rsqrtf(vr.w + 1e-5f);

    #pragma unroll
    for (int r = 0; r < 4; r++) {
        int v = rowbase + w * 4 + r;
        float4 y = make_float4(0.f, 0.f, 0.f, 0.f);
        if (v < n) {
            float aldv = __ldg(&ald_in[v * 4 + head]);
            float4 a = agg_node128(Hh_in, als_in, aldv, head, lane,
                                   g_off[v], g_off[v + 1]);
            y.x = (a.x + bi.x - mn.x) * rsx * gm.x + bt.x;
            y.y = (a.y + bi.y - mn.y) * rsy * gm.y + bt.y;
            y.z = (a.z + bi.z - mn.z) * rsz * gm.z + bt.z;
            y.w = (a.w + bi.w - mn.w) * rsw * gm.w + bt.w;
            y.x = y.x > 0.f ? y.x : expm1f(y.x);
            y.y = y.y > 0.f ? y.y : expm1f(y.y);
            y.z = y.z > 0.f ? y.z : expm1f(y.z);
            y.w = y.w > 0.f ? y.w : expm1f(y.w);
        }
        Asm4[(w * 4 + r) * 32 + lane] = y;
    }
    __syncthreads();

    unsigned long long acc[4];
    #pragma unroll
    for (int r = 0; r < 4; r++) acc[r] = 0ull;

    #pragma unroll 4
    for (int k4 = 0; k4 < 32; k4++) {
        unsigned long long w0 = Wp2s[(2 * k4) * 32 + lane];
        unsigned long long w1 = Wp2s[(2 * k4 + 1) * 32 + lane];
        #pragma unroll
        for (int r = 0; r < 4; r++) {
            ulonglong2 ap = *(const ulonglong2*)&Asm4[(w * 4 + r) * 32 + k4];
            FMA2(acc[r], ap.x, w0);
            FMA2(acc[r], ap.y, w1);
        }
    }

    float asl = asrc[lane], adl = adst[lane];
    #pragma unroll
    for (int r = 0; r < 4; r++) {
        int row = rowbase + w * 4 + r;
        if (row >= n) break;
        float v = f2lo(acc[r]) + f2hi(acc[r]);
        Hh_out[(size_t)row * 32 + lane] = __float2half_rn(v);
        float ps = v * asl;
        float pd = v * adl;
        #pragma unroll
        for (int o = 1; o < 32; o <<= 1) {
            ps += __shfl_xor_sync(0xffffffffu, ps, o);
            pd += __shfl_xor_sync(0xffffffffu, pd, o);
        }
        if (lane == 0) { als_out[row] = ps; ald_out[row] = pd; }
    }
}

// ---------------- K4: layer-2 aggregation (fp16 H) + BN + ELU + classifier ----------
__global__ __launch_bounds__(256) void agg32_kernel(
    const __half* __restrict__ H, const float* __restrict__ als,
    const float* __restrict__ ald,
    const float* __restrict__ bias, const float* __restrict__ gamma,
    const float* __restrict__ beta, const float* __restrict__ mean,
    const float* __restrict__ var,
    const float* __restrict__ Wc, const float* __restrict__ bc,
    float* __restrict__ out, int n)
{
    int v = (blockIdx.x * blockDim.x + threadIdx.x) >> 5;
    if (v >= n) return;
    int lane = threadIdx.x & 31;
    float aldv = __ldg(&ald[v]);
    int s0 = g_off[v], s1 = g_off[v + 1];
    float s = 0.f, acc = 0.f;

    int idx = s0;
    for (; idx + 4 <= s1; idx += 4) {
        int u0 = __ldg(&g_csr[idx]);
        int u1 = __ldg(&g_csr[idx + 1]);
        int u2 = __ldg(&g_csr[idx + 2]);
        int u3 = __ldg(&g_csr[idx + 3]);
        float e0 = __ldg(&als[u0]) + aldv;
        float e1 = __ldg(&als[u1]) + aldv;
        float e2 = __ldg(&als[u2]) + aldv;
        float e3 = __ldg(&als[u3]) + aldv;
        float h0 = __half2float(__ldg(&H[(size_t)u0 * 32 + lane]));
        float h1 = __half2float(__ldg(&H[(size_t)u1 * 32 + lane]));
        float h2 = __half2float(__ldg(&H[(size_t)u2 * 32 + lane]));
        float h3 = __half2float(__ldg(&H[(size_t)u3 * 32 + lane]));
        float w0 = __expf(lrelu(e0));
        float w1 = __expf(lrelu(e1));
        float w2 = __expf(lrelu(e2));
        float w3 = __expf(lrelu(e3));
        s += (w0 + w1) + (w2 + w3);
        acc += w0 * h0 + w1 * h1 + w2 * h2 + w3 * h3;
    }
    for (; idx < s1; idx++) {
        int u = __ldg(&g_csr[idx]);
        float wt = __expf(lrelu(__ldg(&als[u]) + aldv));
        s += wt;
        acc += wt * __half2float(__ldg(&H[(size_t)u * 32 + lane]));
    }

    float y = acc / (s + 1e-16f) + bias[lane];
    y = (y - mean[lane]) * rsqrtf(var[lane] + 1e-5f) * gamma[lane] + beta[lane];
    y = y > 0.f ? y : expm1f(y);
    #pragma unroll
    for (int cc = 0; cc < 10; cc++) {
        float p = y * Wc[lane * 10 + cc];
        #pragma unroll
        for (int o = 16; o; o >>= 1) p += __shfl_xor_sync(0xffffffffu, p, o);
        if (lane == 0) out[(size_t)v * 10 + cc] = p + bc[cc];
    }
}

// ---------------- launch ----------------
extern "C" void kernel_launch(void* const* d_in, const int* in_sizes, int n_in,
                              void* d_out, int out_size) {
    const float* x   = (const float*)d_in[0];
    const int*   ei  = (const int*)d_in[1];
    const float* W0  = (const float*)d_in[2];
    const float* as0 = (const float*)d_in[3];
    const float* ad0 = (const float*)d_in[4];
    const float* b0  = (const float*)d_in[5];
    const float* gm0 = (const float*)d_in[6];
    const float* bt0 = (const float*)d_in[7];
    const float* m0  = (const float*)d_in[8];
    const float* v0  = (const float*)d_in[9];
    const float* W1  = (const float*)d_in[10];
    const float* as1 = (const float*)d_in[11];
    const float* ad1 = (const float*)d_in[12];
    const float* b1  = (const float*)d_in[13];
    const float* gm1 = (const float*)d_in[14];
    const float* bt1 = (const float*)d_in[15];
    const float* m1  = (const float*)d_in[16];
    const float* v1  = (const float*)d_in[17];
    const float* W2  = (const float*)d_in[18];
    const float* as2 = (const float*)d_in[19];
    const float* ad2 = (const float*)d_in[20];
    const float* b2  = (const float*)d_in[21];
    const float* gm2 = (const float*)d_in[22];
    const float* bt2 = (const float*)d_in[23];
    const float* m2  = (const float*)d_in[24];
    const float* v2  = (const float*)d_in[25];
    const float* Wc  = (const float*)d_in[26];
    const float* bc  = (const float*)d_in[27];

    int n = in_sizes[0] / 128;   // 100000
    int e = in_sizes[1] / 2;     // 1600000

    __half *hh0, *hh1, *h2;
    float *als0, *ald0, *als1, *ald1, *als2, *ald2;
    ulonglong2 *wp0, *wp1;
    cudaGetSymbolAddress((void**)&hh0, g_hh0);
    cudaGetSymbolAddress((void**)&hh1, g_hh1);
    cudaGetSymbolAddress((void**)&h2, g_h2);
    cudaGetSymbolAddress((void**)&als0, g_als0);
    cudaGetSymbolAddress((void**)&ald0, g_ald0);
    cudaGetSymbolAddress((void**)&als1, g_als1);
    cudaGetSymbolAddress((void**)&ald1, g_ald1);
    cudaGetSymbolAddress((void**)&als2, g_als2);
    cudaGetSymbolAddress((void**)&ald2, g_ald2);
    cudaGetSymbolAddress((void**)&wp0, g_Wp0);
    cudaGetSymbolAddress((void**)&wp1, g_Wp1);

    // side stream + fork/join events (created once; host-side resources only)
    static cudaStream_t s2 = nullptr;
    static cudaEvent_t evFork = nullptr, evCsr = nullptr;
    if (!s2) {
        cudaStreamCreateWithFlags(&s2, cudaStreamNonBlocking);
        cudaEventCreateWithFlags(&evFork, cudaEventDisableTiming);
        cudaEventCreateWithFlags(&evCsr, cudaEventDisableTiming);
    }

    int nb = (n + 1023) / 1024;
    int eb = (e + 255) / 256;
    int tile_blocks = (n + 31) / 32;   // 3125
    int agg_blocks = (n + 7) / 8;

    // fork: CSR build on s2, overlapped with W prepack + K1 on the main stream
    cudaEventRecord(evFork, 0);
    cudaStreamWaitEvent(s2, evFork, 0);

    zero_deg_kernel<<<(n + 255) / 256, 256, 0, s2>>>(n);
    count_kernel<<<eb, 256, 0, s2>>>(ei, e);
    scan1_kernel<<<nb, 1024, 0, s2>>>(n);
    scan2_kernel<<<1, 128, 0, s2>>>(nb);
    scan3_kernel<<<nb, 1024, 0, s2>>>(n, e);
    fill_kernel<<<eb, 256, 0, s2>>>(ei, e);
    cudaEventRecord(evCsr, s2);

    // main stream: prepack W0/W1, K1 (no CSR dependency)
    packW128_kernel<<<16, 256>>>(W0, wp0);
    packW128_kernel<<<16, 256>>>(W1, wp1);
    gemm128_kernel<<<tile_blocks, 256>>>(
        (const float4*)x, wp0, as0, ad0, (__half2*)hh0, als0, ald0, n);

    // join: fused kernels need the CSR
    cudaStreamWaitEvent(0, evCsr, 0);

    // K2: agg(L0) + BN + ELU + GEMM(W1) + logits
    fused_agg_gemm128_kernel<<<tile_blocks, 256>>>(
        (const uint2*)hh0, als0, ald0, b0, gm0, bt0, m0, v0,
        wp1, as1, ad1, (__half2*)hh1, als1, ald1, n);

    // K3: agg(L1) + BN + ELU + GEMM(W2) + logits
    fused_agg_gemm32_kernel<<<tile_blocks, 256>>>(
        (const uint2*)hh1, als1, ald1, b1, gm1, bt1, m1, v1,
        W2, as2, ad2, h2, als2, ald2, n);

    // K4: agg(L2) + BN + ELU + classifier
    agg32_kernel<<<agg_blocks, 256>>>(
        h2, als2, ald2, b2, gm2, bt2, m2, v2, Wc, bc, (float*)d_out, n);
}

// round 12
// speedup vs baseline: 1.1391x; 1.1391x over previous
#include <cuda_runtime.h>
#include <cuda_fp16.h>
#include <math.h>
#include <stdint.h>

#define NNODES 100000
#define NEDGES 1600000

// packed f32x2 FMA: d = a*b + d (elementwise on 2 packed fp32)
#define FMA2(d, a, b) \
    asm("fma.rn.f32x2 %0, %1, %2, %0;" : "+l"(d) : "l"(a), "l"(b))

__device__ __forceinline__ float f2lo(unsigned long long v) {
    return __uint_as_float((unsigned)(v & 0xffffffffull));
}
__device__ __forceinline__ float f2hi(unsigned long long v) {
    return __uint_as_float((unsigned)(v >> 32));
}
__device__ __forceinline__ unsigned long long packf2(float lo, float hi) {
    return (unsigned long long)__float_as_uint(lo) |
           ((unsigned long long)__float_as_uint(hi) << 32);
}
__device__ __forceinline__ float lrelu(float x) {
    return x > 0.f ? x : 0.2f * x;
}

// ---------------- scratch (device globals) ----------------
__device__ __align__(128) __half g_feat[NNODES * 128];  // fp16 aggregated features
__device__ __align__(128) __half g_hh[NNODES * 128];    // fp16 H for layers 0/1
__device__ __align__(128) __half g_h2[NNODES * 32];     // fp16 H for layer 2
__device__ __align__(128) ulonglong2 g_Wp0[4096];       // prepacked W0 (64KB)
__device__ __align__(128) ulonglong2 g_Wp1[4096];       // prepacked W1 (64KB)
__device__ float g_als[NNODES * 4];
__device__ float g_ald[NNODES * 4];
__device__ int   g_deg[NNODES];
__device__ int   g_off[NNODES + 1];
__device__ int   g_cur[NNODES];
__device__ int   g_bsum[128];
__device__ int   g_csr[NEDGES];

// ---------------- CSR build ----------------
__global__ void zero_deg_kernel(int n) {
    int i = blockIdx.x * blockDim.x + threadIdx.x;
    if (i < n) g_deg[i] = 0;
}
__global__ void count_kernel(const int* __restrict__ ei, int e) {
    int i = blockIdx.x * blockDim.x + threadIdx.x;
    if (i < e) atomicAdd(&g_deg[ei[e + i]], 1);
}
__global__ void scan1_kernel(int n) {
    __shared__ int sm[1024];
    int i = blockIdx.x * 1024 + threadIdx.x;
    int v = (i < n) ? g_deg[i] : 0;
    sm[threadIdx.x] = v;
    __syncthreads();
    #pragma unroll
    for (int d = 1; d < 1024; d <<= 1) {
        int t = (threadIdx.x >= d) ? sm[threadIdx.x - d] : 0;
        __syncthreads();
        sm[threadIdx.x] += t;
        __syncthreads();
    }
    if (i < n) g_off[i] = sm[threadIdx.x] - v;
    if (threadIdx.x == 1023) g_bsum[blockIdx.x] = sm[1023];
}
__global__ void scan2_kernel(int nb) {
    __shared__ int sm[128];
    int t = threadIdx.x;
    int v = (t < nb) ? g_bsum[t] : 0;
    sm[t] = v;
    __syncthreads();
    #pragma unroll
    for (int d = 1; d < 128; d <<= 1) {
        int tv = (t >= d) ? sm[t - d] : 0;
        __syncthreads();
        sm[t] += tv;
        __syncthreads();
    }
    if (t < nb) g_bsum[t] = sm[t] - v;
}
__global__ void scan3_kernel(int n, int e) {
    int i = blockIdx.x * 1024 + threadIdx.x;
    if (i < n) {
        int o = g_off[i] + g_bsum[blockIdx.x];
        g_off[i] = o;
        g_cur[i] = o;
    }
    if (i == 0) g_off[n] = e;
}
__global__ void fill_kernel(const int* __restrict__ ei, int e) {
    int i = blockIdx.x * blockDim.x + threadIdx.x;
    if (i < e) {
        int src = ei[i];
        int dst = ei[e + i];
        int pos = atomicAdd(&g_cur[dst], 1);
        g_csr[pos] = src;
    }
}

// ---------------- W prepack: Wp[(k2*2+half)*32 + l] for gemm128 ----------------
__global__ void packW128_kernel(const float* __restrict__ W, ulonglong2* __restrict__ Wp) {
    int i = blockIdx.x * 256 + threadIdx.x;   // < 4096
    int k2 = i >> 6;
    int half_ = (i >> 5) & 1;
    int l = i & 31;
    int c0 = 2 * l + 64 * half_;
    ulonglong2 p;
    p.x = packf2(W[(2 * k2) * 128 + c0], W[(2 * k2 + 1) * 128 + c0]);
    p.y = packf2(W[(2 * k2) * 128 + c0 + 1], W[(2 * k2 + 1) * 128 + c0 + 1]);
    Wp[i] = p;
}

// ---------------- GEMM 128->128: W via L1-resident global, 3 CTAs/SM ---------------
// HALFIN=0: A is float4 rows; HALFIN=1: A is fp16 rows (uint2 of 4 halves).
template <int HALFIN>
__global__ __launch_bounds__(256, 3) void gemm128_kernel(
    const void* __restrict__ Ain, const ulonglong2* __restrict__ Wp,
    const float* __restrict__ asrc, const float* __restrict__ adst,
    __half2* __restrict__ Hh, float* __restrict__ als, float* __restrict__ ald, int n)
{
    __shared__ float4 Asm4[1024];   // 32 rows x 32 float4 = 16KB
    int tid = threadIdx.x;
    int rowbase = blockIdx.x * 32;
    #pragma unroll
    for (int i = tid; i < 1024; i += 256) {
        int row = rowbase + (i >> 5);
        float4 a = make_float4(0.f, 0.f, 0.f, 0.f);
        if (row < n) {
            if (HALFIN) {
                uint2 p = ((const uint2*)Ain)[(size_t)row * 32 + (i & 31)];
                float2 lo = __half22float2(*(__half2*)&p.x);
                float2 hi = __half22float2(*(__half2*)&p.y);
                a = make_float4(lo.x, lo.y, hi.x, hi.y);
            } else {
                a = ((const float4*)Ain)[(size_t)row * 32 + (i & 31)];
            }
        }
        Asm4[i] = a;
    }
    __syncthreads();

    int w = tid >> 5, lane = tid & 31;
    unsigned long long acc[4][4];
    #pragma unroll
    for (int r = 0; r < 4; r++)
        #pragma unroll
        for (int c = 0; c < 4; c++) acc[r][c] = 0ull;

    #pragma unroll 4
    for (int k4 = 0; k4 < 32; k4++) {
        ulonglong2 wa0 = __ldg(&Wp[((2 * k4) * 2 + 0) * 32 + lane]);
        ulonglong2 wb0 = __ldg(&Wp[((2 * k4) * 2 + 1) * 32 + lane]);
        ulonglong2 wa1 = __ldg(&Wp[((2 * k4 + 1) * 2 + 0) * 32 + lane]);
        ulonglong2 wb1 = __ldg(&Wp[((2 * k4 + 1) * 2 + 1) * 32 + lane]);
        #pragma unroll
        for (int r = 0; r < 4; r++) {
            ulonglong2 ap = *(const ulonglong2*)&Asm4[(w * 4 + r) * 32 + k4];
            FMA2(acc[r][0], ap.x, wa0.x);
            FMA2(acc[r][1], ap.x, wa0.y);
            FMA2(acc[r][2], ap.x, wb0.x);
            FMA2(acc[r][3], ap.x, wb0.y);
            FMA2(acc[r][0], ap.y, wa1.x);
            FMA2(acc[r][1], ap.y, wa1.y);
            FMA2(acc[r][2], ap.y, wb1.x);
            FMA2(acc[r][3], ap.y, wb1.y);
        }
    }

    // epilogue: cols {2L,2L+1} (head hA = lane>>4) and {2L+64,2L+65} (head hA+2)
    int c0 = 2 * lane;
    float as0 = asrc[c0], as1 = asrc[c0 + 1], as2_ = asrc[c0 + 64], as3 = asrc[c0 + 65];
    float ad0 = adst[c0], ad1 = adst[c0 + 1], ad2_ = adst[c0 + 64], ad3 = adst[c0 + 65];
    int hA = lane >> 4;
    #pragma unroll
    for (int r = 0; r < 4; r++) {
        int row = rowbase + w * 4 + r;
        if (row >= n) break;
        float v0 = f2lo(acc[r][0]) + f2hi(acc[r][0]);
        float v1 = f2lo(acc[r][1]) + f2hi(acc[r][1]);
        float v2 = f2lo(acc[r][2]) + f2hi(acc[r][2]);
        float v3 = f2lo(acc[r][3]) + f2hi(acc[r][3]);
        Hh[(size_t)row * 64 + lane] = __floats2half2_rn(v0, v1);
        Hh[(size_t)row * 64 + 32 + lane] = __floats2half2_rn(v2, v3);
        float psl = v0 * as0 + v1 * as1;
        float psh = v2 * as2_ + v3 * as3;
        float pdl = v0 * ad0 + v1 * ad1;
        float pdh = v2 * ad2_ + v3 * ad3;
        #pragma unroll
        for (int o = 1; o < 16; o <<= 1) {
            psl += __shfl_xor_sync(0xffffffffu, psl, o);
            psh += __shfl_xor_sync(0xffffffffu, psh, o);
            pdl += __shfl_xor_sync(0xffffffffu, pdl, o);
            pdh += __shfl_xor_sync(0xffffffffu, pdh, o);
        }
        if ((lane & 15) == 0) {
            als[row * 4 + hA] = psl;
            als[row * 4 + hA + 2] = psh;
            ald[row * 4 + hA] = pdl;
            ald[row * 4 + hA + 2] = pdh;
        }
    }
}

// ---------------- GEMM 128->32 (fp16 A in, packed f32x2) -> fp16 H + logits --------
__global__ __launch_bounds__(256) void gemm32_kernel(
    const uint2* __restrict__ Ah, const float* __restrict__ W,
    const float* __restrict__ asrc, const float* __restrict__ adst,
    __half* __restrict__ Hh, float* __restrict__ als, float* __restrict__ ald, int n)
{
    __shared__ unsigned long long Wp[64 * 32];   // 16KB, lane-contiguous
    __shared__ float4 Asm4[2048];                // 32KB
    int tid = threadIdx.x;
    #pragma unroll 2
    for (int i = tid; i < 2048; i += 256) {
        int k2 = i >> 5, l = i & 31;
        Wp[i] = packf2(W[(k2 * 2) * 32 + l], W[(k2 * 2 + 1) * 32 + l]);
    }
    int rowbase = blockIdx.x * 64;
    #pragma unroll 2
    for (int i = tid; i < 2048; i += 256) {
        int row = rowbase + (i >> 5);
        float4 a = make_float4(0.f, 0.f, 0.f, 0.f);
        if (row < n) {
            uint2 p = Ah[(size_t)row * 32 + (i & 31)];
            float2 lo = __half22float2(*(__half2*)&p.x);
            float2 hi = __half22float2(*(__half2*)&p.y);
            a = make_float4(lo.x, lo.y, hi.x, hi.y);
        }
        Asm4[i] = a;
    }
    __syncthreads();

    int w = tid >> 5, lane = tid & 31;
    unsigned long long acc[8];
    #pragma unroll
    for (int r = 0; r < 8; r++) acc[r] = 0ull;

    #pragma unroll 4
    for (int k4 = 0; k4 < 32; k4++) {
        unsigned long long w0 = Wp[(2 * k4) * 32 + lane];
        unsigned long long w1 = Wp[(2 * k4 + 1) * 32 + lane];
        #pragma unroll
        for (int r = 0; r < 8; r++) {
            ulonglong2 ap = *(const ulonglong2*)&Asm4[(w * 8 + r) * 32 + k4];
            FMA2(acc[r], ap.x, w0);
            FMA2(acc[r], ap.y, w1);
        }
    }

    float asl = asrc[lane], adl = adst[lane];
    #pragma unroll
    for (int r = 0; r < 8; r++) {
        int row = rowbase + w * 8 + r;
        if (row >= n) break;
        float v = f2lo(acc[r]) + f2hi(acc[r]);
        Hh[(size_t)row * 32 + lane] = __float2half_rn(v);
        float ps = v * asl;
        float pd = v * adl;
        #pragma unroll
        for (int o = 1; o < 32; o <<= 1) {
            ps += __shfl_xor_sync(0xffffffffu, ps, o);
            pd += __shfl_xor_sync(0xffffffffu, pd, o);
        }
        if (lane == 0) { als[row] = ps; ald[row] = pd; }
    }
}

// ---------------- aggregation 4 heads x 32ch, fp16 H gathers -> fp16 feat ----------
__global__ __launch_bounds__(256) void agg128_kernel(
    const uint2* __restrict__ Hh, const float* __restrict__ als,
    const float* __restrict__ ald,
    const float* __restrict__ bias, const float* __restrict__ gamma,
    const float* __restrict__ beta, const float* __restrict__ mean,
    const float* __restrict__ var,
    uint2* __restrict__ out2, int n)
{
    int v = (blockIdx.x * blockDim.x + threadIdx.x) >> 5;
    if (v >= n) return;
    int lane = threadIdx.x & 31;
    int head = lane >> 3;
    float aldv = __ldg(&ald[v * 4 + head]);
    int s0 = g_off[v], s1 = g_off[v + 1];
    float s = 0.f;
    float4 acc = make_float4(0.f, 0.f, 0.f, 0.f);

    int idx = s0;
    for (; idx + 4 <= s1; idx += 4) {
        int u0 = __ldg(&g_csr[idx]);
        int u1 = __ldg(&g_csr[idx + 1]);
        int u2 = __ldg(&g_csr[idx + 2]);
        int u3 = __ldg(&g_csr[idx + 3]);
        float e0 = __ldg(&als[u0 * 4 + head]) + aldv;
        float e1 = __ldg(&als[u1 * 4 + head]) + aldv;
        float e2 = __ldg(&als[u2 * 4 + head]) + aldv;
        float e3 = __ldg(&als[u3 * 4 + head]) + aldv;
        uint2 p0 = __ldg(&Hh[(size_t)u0 * 32 + lane]);
        uint2 p1 = __ldg(&Hh[(size_t)u1 * 32 + lane]);
        uint2 p2 = __ldg(&Hh[(size_t)u2 * 32 + lane]);
        uint2 p3 = __ldg(&Hh[(size_t)u3 * 32 + lane]);
        float w0 = __expf(lrelu(e0));
        float w1 = __expf(lrelu(e1));
        float w2 = __expf(lrelu(e2));
        float w3 = __expf(lrelu(e3));
        s += (w0 + w1) + (w2 + w3);
        float2 a0 = __half22float2(*(__half2*)&p0.x), b0 = __half22float2(*(__half2*)&p0.y);
        float2 a1 = __half22float2(*(__half2*)&p1.x), b1 = __half22float2(*(__half2*)&p1.y);
        float2 a2 = __half22float2(*(__half2*)&p2.x), b2 = __half22float2(*(__half2*)&p2.y);
        float2 a3 = __half22float2(*(__half2*)&p3.x), b3 = __half22float2(*(__half2*)&p3.y);
        acc.x += w0 * a0.x + w1 * a1.x + w2 * a2.x + w3 * a3.x;
        acc.y += w0 * a0.y + w1 * a1.y + w2 * a2.y + w3 * a3.y;
        acc.z += w0 * b0.x + w1 * b1.x + w2 * b2.x + w3 * b3.x;
        acc.w += w0 * b0.y + w1 * b1.y + w2 * b2.y + w3 * b3.y;
    }
    for (; idx < s1; idx++) {
        int u = __ldg(&g_csr[idx]);
        float wt = __expf(lrelu(__ldg(&als[u * 4 + head]) + aldv));
        uint2 p = __ldg(&Hh[(size_t)u * 32 + lane]);
        float2 a = __half22float2(*(__half2*)&p.x), b = __half22float2(*(__half2*)&p.y);
        s += wt;
        acc.x += wt * a.x;
        acc.y += wt * a.y;
        acc.z += wt * b.x;
        acc.w += wt * b.y;
    }

    float inv = 1.f / (s + 1e-16f);
    float4 bi = ((const float4*)bias)[lane];
    float4 mn = ((const float4*)mean)[lane];
    float4 vr = ((const float4*)var)[lane];
    float4 gm = ((const float4*)gamma)[lane];
    float4 bt = ((const float4*)beta)[lane];
    float4 y;
    y.x = (acc.x * inv + bi.x - mn.x) * rsqrtf(vr.x + 1e-5f) * gm.x + bt.x;
    y.y = (acc.y * inv + bi.y - mn.y) * rsqrtf(vr.y + 1e-5f) * gm.y + bt.y;
    y.z = (acc.z * inv + bi.z - mn.z) * rsqrtf(vr.z + 1e-5f) * gm.z + bt.z;
    y.w = (acc.w * inv + bi.w - mn.w) * rsqrtf(vr.w + 1e-5f) * gm.w + bt.w;
    y.x = y.x > 0.f ? y.x : expm1f(y.x);
    y.y = y.y > 0.f ? y.y : expm1f(y.y);
    y.z = y.z > 0.f ? y.z : expm1f(y.z);
    y.w = y.w > 0.f ? y.w : expm1f(y.w);
    uint2 o;
    *(__half2*)&o.x = __floats2half2_rn(y.x, y.y);
    *(__half2*)&o.y = __floats2half2_rn(y.z, y.w);
    out2[(size_t)v * 32 + lane] = o;
}

// ---------------- layer-2 aggregation (fp16 H) + BN + ELU + classifier --------------
__global__ __launch_bounds__(256) void agg32_kernel(
    const __half* __restrict__ H, const float* __restrict__ als,
    const float* __restrict__ ald,
    const float* __restrict__ bias, const float* __restrict__ gamma,
    const float* __restrict__ beta, const float* __restrict__ mean,
    const float* __restrict__ var,
    const float* __restrict__ Wc, const float* __restrict__ bc,
    float* __restrict__ out, int n)
{
    int v = (blockIdx.x * blockDim.x + threadIdx.x) >> 5;
    if (v >= n) return;
    int lane = threadIdx.x & 31;
    float aldv = __ldg(&ald[v]);
    int s0 = g_off[v], s1 = g_off[v + 1];
    float s = 0.f, acc = 0.f;

    int idx = s0;
    for (; idx + 4 <= s1; idx += 4) {
        int u0 = __ldg(&g_csr[idx]);
        int u1 = __ldg(&g_csr[idx + 1]);
        int u2 = __ldg(&g_csr[idx + 2]);
        int u3 = __ldg(&g_csr[idx + 3]);
        float e0 = __ldg(&als[u0]) + aldv;
        float e1 = __ldg(&als[u1]) + aldv;
        float e2 = __ldg(&als[u2]) + aldv;
        float e3 = __ldg(&als[u3]) + aldv;
        float h0 = __half2float(__ldg(&H[(size_t)u0 * 32 + lane]));
        float h1 = __half2float(__ldg(&H[(size_t)u1 * 32 + lane]));
        float h2 = __half2float(__ldg(&H[(size_t)u2 * 32 + lane]));
        float h3 = __half2float(__ldg(&H[(size_t)u3 * 32 + lane]));
        float w0 = __expf(lrelu(e0));
        float w1 = __expf(lrelu(e1));
        float w2 = __expf(lrelu(e2));
        float w3 = __expf(lrelu(e3));
        s += (w0 + w1) + (w2 + w3);
        acc += w0 * h0 + w1 * h1 + w2 * h2 + w3 * h3;
    }
    for (; idx < s1; idx++) {
        int u = __ldg(&g_csr[idx]);
        float wt = __expf(lrelu(__ldg(&als[u]) + aldv));
        s += wt;
        acc += wt * __half2float(__ldg(&H[(size_t)u * 32 + lane]));
    }

    float y = acc / (s + 1e-16f) + bias[lane];
    y = (y - mean[lane]) * rsqrtf(var[lane] + 1e-5f) * gamma[lane] + beta[lane];
    y = y > 0.f ? y : expm1f(y);
    #pragma unroll
    for (int cc = 0; cc < 10; cc++) {
        float p = y * Wc[lane * 10 + cc];
        #pragma unroll
        for (int o = 16; o; o >>= 1) p += __shfl_xor_sync(0xffffffffu, p, o);
        if (lane == 0) out[(size_t)v * 10 + cc] = p + bc[cc];
    }
}

// ---------------- launch ----------------
extern "C" void kernel_launch(void* const* d_in, const int* in_sizes, int n_in,
                              void* d_out, int out_size) {
    const float* x   = (const float*)d_in[0];
    const int*   ei  = (const int*)d_in[1];
    const float* W0  = (const float*)d_in[2];
    const float* as0 = (const float*)d_in[3];
    const float* ad0 = (const float*)d_in[4];
    const float* b0  = (const float*)d_in[5];
    const float* gm0 = (const float*)d_in[6];
    const float* bt0 = (const float*)d_in[7];
    const float* m0  = (const float*)d_in[8];
    const float* v0  = (const float*)d_in[9];
    const float* W1  = (const float*)d_in[10];
    const float* as1 = (const float*)d_in[11];
    const float* ad1 = (const float*)d_in[12];
    const float* b1  = (const float*)d_in[13];
    const float* gm1 = (const float*)d_in[14];
    const float* bt1 = (const float*)d_in[15];
    const float* m1  = (const float*)d_in[16];
    const float* v1  = (const float*)d_in[17];
    const float* W2  = (const float*)d_in[18];
    const float* as2 = (const float*)d_in[19];
    const float* ad2 = (const float*)d_in[20];
    const float* b2  = (const float*)d_in[21];
    const float* gm2 = (const float*)d_in[22];
    const float* bt2 = (const float*)d_in[23];
    const float* m2  = (const float*)d_in[24];
    const float* v2  = (const float*)d_in[25];
    const float* Wc  = (const float*)d_in[26];
    const float* bc  = (const float*)d_in[27];

    int n = in_sizes[0] / 128;   // 100000
    int e = in_sizes[1] / 2;     // 1600000

    __half *feat, *hh, *h2;
    float *als, *ald;
    ulonglong2 *wp0, *wp1;
    cudaGetSymbolAddress((void**)&feat, g_feat);
    cudaGetSymbolAddress((void**)&hh, g_hh);
    cudaGetSymbolAddress((void**)&h2, g_h2);
    cudaGetSymbolAddress((void**)&als, g_als);
    cudaGetSymbolAddress((void**)&ald, g_ald);
    cudaGetSymbolAddress((void**)&wp0, g_Wp0);
    cudaGetSymbolAddress((void**)&wp1, g_Wp1);

    // side stream + fork/join events (created once; host-side resources only)
    static cudaStream_t s2 = nullptr;
    static cudaEvent_t evFork = nullptr, evCsr = nullptr;
    if (!s2) {
        cudaStreamCreateWithFlags(&s2, cudaStreamNonBlocking);
        cudaEventCreateWithFlags(&evFork, cudaEventDisableTiming);
        cudaEventCreateWithFlags(&evCsr, cudaEventDisableTiming);
    }

    int nb = (n + 1023) / 1024;
    int eb = (e + 255) / 256;
    int g128_blocks = (n + 31) / 32;
    int g32_blocks = (n + 63) / 64;
    int agg_blocks = (n + 7) / 8;

    // fork: CSR build on s2, overlapped with W prepack + layer-0 GEMM on main stream
    cudaEventRecord(evFork, 0);
    cudaStreamWaitEvent(s2, evFork, 0);

    zero_deg_kernel<<<(n + 255) / 256, 256, 0, s2>>>(n);
    count_kernel<<<eb, 256, 0, s2>>>(ei, e);
    scan1_kernel<<<nb, 1024, 0, s2>>>(n);
    scan2_kernel<<<1, 128, 0, s2>>>(nb);
    scan3_kernel<<<nb, 1024, 0, s2>>>(n, e);
    fill_kernel<<<eb, 256, 0, s2>>>(ei, e);
    cudaEventRecord(evCsr, s2);

    // main stream: prepack W0/W1, then layer-0 GEMM (fp32 input; no CSR dependency)
    packW128_kernel<<<16, 256>>>(W0, wp0);
    packW128_kernel<<<16, 256>>>(W1, wp1);
    gemm128_kernel<0><<<g128_blocks, 256>>>(
        x, wp0, as0, ad0, (__half2*)hh, als, ald, n);

    // join: aggregation needs both the GEMM and the CSR
    cudaStreamWaitEvent(0, evCsr, 0);

    // layer 0 aggregation -> fp16 feat
    agg128_kernel<<<agg_blocks, 256>>>(
        (const uint2*)hh, als, ald, b0, gm0, bt0, m0, v0, (uint2*)feat, n);

    // layer 1 (fp16 input)
    gemm128_kernel<1><<<g128_blocks, 256>>>(
        feat, wp1, as1, ad1, (__half2*)hh, als, ald, n);
    agg128_kernel<<<agg_blocks, 256>>>(
        (const uint2*)hh, als, ald, b1, gm1, bt1, m1, v1, (uint2*)feat, n);

    // layer 2 (single head, fp16 in/out) + classifier
    gemm32_kernel<<<g32_blocks, 256>>>(
        (const uint2*)feat, W2, as2, ad2, h2, als, ald, n);
    agg32_kernel<<<agg_blocks, 256>>>(
        h2, als, ald, b2, gm2, bt2, m2, v2, Wc, bc, (float*)d_out, n);
}

// round 13
// speedup vs baseline: 1.3197x; 1.1586x over previous
#include <cuda_runtime.h>
#include <cuda_fp16.h>
#include <cuda_bf16.h>
#include <math.h>
#include <stdint.h>

#define NNODES 100000
#define NEDGES 1600000

// packed f32x2 FMA: d = a*b + d (elementwise on 2 packed fp32)
#define FMA2(d, a, b) \
    asm("fma.rn.f32x2 %0, %1, %2, %0;" : "+l"(d) : "l"(a), "l"(b))

__device__ __forceinline__ float f2lo(unsigned long long v) {
    return __uint_as_float((unsigned)(v & 0xffffffffull));
}
__device__ __forceinline__ float f2hi(unsigned long long v) {
    return __uint_as_float((unsigned)(v >> 32));
}
__device__ __forceinline__ unsigned long long packf2(float lo, float hi) {
    return (unsigned long long)__float_as_uint(lo) |
           ((unsigned long long)__float_as_uint(hi) << 32);
}
__device__ __forceinline__ float lrelu(float x) {
    return x > 0.f ? x : 0.2f * x;
}
__device__ __forceinline__ uint32_t packbf2(__nv_bfloat16 a, __nv_bfloat16 b) {
    return (uint32_t)__bfloat16_as_ushort(a) | ((uint32_t)__bfloat16_as_ushort(b) << 16);
}

// bf16 tensor-core mma: m16n8k16, fp32 accumulate (base sm_80 feature, no 'a' gate)
__device__ __forceinline__ void mma_bf16(float* c, uint32_t a0, uint32_t a1,
                                         uint32_t a2, uint32_t a3,
                                         uint32_t b0, uint32_t b1) {
    asm volatile(
        "mma.sync.aligned.m16n8k16.row.col.f32.bf16.bf16.f32 "
        "{%0,%1,%2,%3}, {%4,%5,%6,%7}, {%8,%9}, {%0,%1,%2,%3};"
        : "+f"(c[0]), "+f"(c[1]), "+f"(c[2]), "+f"(c[3])
        : "r"(a0), "r"(a1), "r"(a2), "r"(a3), "r"(b0), "r"(b1));
}

// ---------------- scratch (device globals) ----------------
__device__ __align__(128) __half g_feat[NNODES * 128];  // fp16 aggregated features
__device__ __align__(128) __half g_hh[NNODES * 128];    // fp16 H for layers 0/1
__device__ __align__(128) __half g_h2[NNODES * 32];     // fp16 H for layer 2
__device__ __align__(128) uint2 g_WfH0[4096];           // W0 hi B-fragments (32KB)
__device__ __align__(128) uint2 g_WfL0[4096];           // W0 lo B-fragments
__device__ __align__(128) uint2 g_WfH1[4096];           // W1 hi
__device__ __align__(128) uint2 g_WfL1[4096];           // W1 lo
__device__ float g_als[NNODES * 4];
__device__ float g_ald[NNODES * 4];
__device__ int   g_deg[NNODES];
__device__ int   g_off[NNODES + 1];
__device__ int   g_cur[NNODES];
__device__ int   g_bsum[128];
__device__ int   g_csr[NEDGES];

// ---------------- CSR build ----------------
__global__ void zero_deg_kernel(int n) {
    int i = blockIdx.x * blockDim.x + threadIdx.x;
    if (i < n) g_deg[i] = 0;
}
__global__ void count_kernel(const int* __restrict__ ei, int e) {
    int i = blockIdx.x * blockDim.x + threadIdx.x;
    if (i < e) atomicAdd(&g_deg[ei[e + i]], 1);
}
__global__ void scan1_kernel(int n) {
    __shared__ int sm[1024];
    int i = blockIdx.x * 1024 + threadIdx.x;
    int v = (i < n) ? g_deg[i] : 0;
    sm[threadIdx.x] = v;
    __syncthreads();
    #pragma unroll
    for (int d = 1; d < 1024; d <<= 1) {
        int t = (threadIdx.x >= d) ? sm[threadIdx.x - d] : 0;
        __syncthreads();
        sm[threadIdx.x] += t;
        __syncthreads();
    }
    if (i < n) g_off[i] = sm[threadIdx.x] - v;
    if (threadIdx.x == 1023) g_bsum[blockIdx.x] = sm[1023];
}
__global__ void scan2_kernel(int nb) {
    __shared__ int sm[128];
    int t = threadIdx.x;
    int v = (t < nb) ? g_bsum[t] : 0;
    sm[t] = v;
    __syncthreads();
    #pragma unroll
    for (int d = 1; d < 128; d <<= 1) {
        int tv = (t >= d) ? sm[t - d] : 0;
        __syncthreads();
        sm[t] += tv;
        __syncthreads();
    }
    if (t < nb) g_bsum[t] = sm[t] - v;
}
__global__ void scan3_kernel(int n, int e) {
    int i = blockIdx.x * 1024 + threadIdx.x;
    if (i < n) {
        int o = g_off[i] + g_bsum[blockIdx.x];
        g_off[i] = o;
        g_cur[i] = o;
    }
    if (i == 0) g_off[n] = e;
}
__global__ void fill_kernel(const int* __restrict__ ei, int e) {
    int i = blockIdx.x * blockDim.x + threadIdx.x;
    if (i < e) {
        int src = ei[i];
        int dst = ei[e + i];
        int pos = atomicAdd(&g_cur[dst], 1);
        g_csr[pos] = src;
    }
}

// ---------------- W fragment prepack (bf16 hi/lo, m16n8k16 B layout) --------------
// tile = kt*16 + nt (kt<8, nt<16). Lane: tid4 = lane&3, grp = lane>>2.
// B frag: reg0 = {W[k0][n], W[k0+1][n]}, reg1 = {W[k0+8][n], W[k0+9][n]}
// with k0 = kt*16 + tid4*2, n = nt*8 + grp.
__global__ void packWfrag_kernel(const float* __restrict__ W,
                                 uint2* __restrict__ wfh, uint2* __restrict__ wfl) {
    int i = blockIdx.x * 256 + threadIdx.x;   // < 4096
    int lane = i & 31, tile = i >> 5;
    int kt = tile >> 4, nt = tile & 15;
    int tid4 = lane & 3, grp = lane >> 2;
    int n = nt * 8 + grp;
    int k0 = kt * 16 + tid4 * 2;
    float w00 = W[k0 * 128 + n];
    float w01 = W[(k0 + 1) * 128 + n];
    float w08 = W[(k0 + 8) * 128 + n];
    float w09 = W[(k0 + 9) * 128 + n];
    __nv_bfloat16 h00 = __float2bfloat16_rn(w00);
    __nv_bfloat16 h01 = __float2bfloat16_rn(w01);
    __nv_bfloat16 h08 = __float2bfloat16_rn(w08);
    __nv_bfloat16 h09 = __float2bfloat16_rn(w09);
    __nv_bfloat16 l00 = __float2bfloat16_rn(w00 - __bfloat162float(h00));
    __nv_bfloat16 l01 = __float2bfloat16_rn(w01 - __bfloat162float(h01));
    __nv_bfloat16 l08 = __float2bfloat16_rn(w08 - __bfloat162float(h08));
    __nv_bfloat16 l09 = __float2bfloat16_rn(w09 - __bfloat162float(h09));
    uint2 ph, pl;
    ph.x = packbf2(h00, h01); ph.y = packbf2(h08, h09);
    pl.x = packbf2(l00, l01); pl.y = packbf2(l08, l09);
    wfh[i] = ph;
    wfl[i] = pl;
}

// ---------------- GEMM 128->128 via bf16 tensor cores (3-pass hi/lo) ---------------
// CTA = 64 rows, 8 warps. Warp w: mtile = w&3 (16 rows), nhalf = w>>2 (64 cols).
// A staged in smem as bf16 hi/lo, row stride 136 halves (272B, conflict-free).
// HALFIN=0: A fp32; HALFIN=1: A fp16.
#define ASTRIDE 136
template <int HALFIN>
__global__ __launch_bounds__(256) void gemm128_mma_kernel(
    const void* __restrict__ Ain,
    const uint2* __restrict__ wfh, const uint2* __restrict__ wfl,
    const float* __restrict__ asrc, const float* __restrict__ adst,
    __half2* __restrict__ Hh, float* __restrict__ als, float* __restrict__ ald, int n)
{
    __shared__ __nv_bfloat16 Ahi[64 * ASTRIDE];
    __shared__ __nv_bfloat16 Alo[64 * ASTRIDE];
    int tid = threadIdx.x;
    int rowbase = blockIdx.x * 64;

    // stage A -> bf16 hi/lo
    for (int i = tid; i < 8192; i += 256) {
        int r = i >> 7, c = i & 127;
        int row = rowbase + r;
        float a = 0.f;
        if (row < n) {
            if (HALFIN) a = __half2float(((const __half*)Ain)[(size_t)row * 128 + c]);
            else        a = ((const float*)Ain)[(size_t)row * 128 + c];
        }
        __nv_bfloat16 h = __float2bfloat16_rn(a);
        __nv_bfloat16 l = __float2bfloat16_rn(a - __bfloat162float(h));
        Ahi[r * ASTRIDE + c] = h;
        Alo[r * ASTRIDE + c] = l;
    }
    __syncthreads();

    int w = tid >> 5, lane = tid & 31;
    int mt = w & 3, nhalf = w >> 2;
    int tid4 = lane & 3, grp = lane >> 2;
    int mbase = mt * 16;

    float acc[8][4];
    #pragma unroll
    for (int t = 0; t < 8; t++)
        #pragma unroll
        for (int c = 0; c < 4; c++) acc[t][c] = 0.f;

    const uint32_t* Ah32 = (const uint32_t*)Ahi;
    const uint32_t* Al32 = (const uint32_t*)Alo;
    // base half-offsets for A frag (even cols -> aligned uint32)
    int ra = (mbase + grp) * ASTRIDE;
    int rb = (mbase + grp + 8) * ASTRIDE;

    #pragma unroll
    for (int kt = 0; kt < 8; kt++) {
        int k0 = kt * 16 + tid4 * 2;
        uint32_t ah0 = Ah32[(ra + k0) >> 1];
        uint32_t ah1 = Ah32[(rb + k0) >> 1];
        uint32_t ah2 = Ah32[(ra + k0 + 8) >> 1];
        uint32_t ah3 = Ah32[(rb + k0 + 8) >> 1];
        uint32_t al0 = Al32[(ra + k0) >> 1];
        uint32_t al1 = Al32[(rb + k0) >> 1];
        uint32_t al2 = Al32[(ra + k0 + 8) >> 1];
        uint32_t al3 = Al32[(rb + k0 + 8) >> 1];
        #pragma unroll
        for (int nt = 0; nt < 8; nt++) {
            int tile = kt * 16 + nhalf * 8 + nt;
            uint2 bh = __ldg(&wfh[tile * 32 + lane]);
            uint2 bl = __ldg(&wfl[tile * 32 + lane]);
            mma_bf16(acc[nt], ah0, ah1, ah2, ah3, bh.x, bh.y);
            mma_bf16(acc[nt], ah0, ah1, ah2, ah3, bl.x, bl.y);
            mma_bf16(acc[nt], al0, al1, al2, al3, bh.x, bh.y);
        }
    }

    // epilogue: lane holds rows (mbase+grp, +8), cols cb+tid4*2, +1 per ntile
    int row0 = rowbase + mbase + grp;
    int row1 = row0 + 8;
    float psA0 = 0.f, psA1 = 0.f, psB0 = 0.f, psB1 = 0.f;
    float pdA0 = 0.f, pdA1 = 0.f, pdB0 = 0.f, pdB1 = 0.f;
    #pragma unroll
    for (int nt = 0; nt < 8; nt++) {
        int cb = nhalf * 64 + nt * 8 + tid4 * 2;
        float c0 = acc[nt][0], c1 = acc[nt][1], c2 = acc[nt][2], c3 = acc[nt][3];
        if (row0 < n) Hh[(size_t)row0 * 64 + (cb >> 1)] = __floats2half2_rn(c0, c1);
        if (row1 < n) Hh[(size_t)row1 * 64 + (cb >> 1)] = __floats2half2_rn(c2, c3);
        float s0 = asrc[cb], s1 = asrc[cb + 1];
        float d0 = adst[cb], d1 = adst[cb + 1];
        float ps0 = c0 * s0 + c1 * s1, ps1 = c2 * s0 + c3 * s1;
        float pd0 = c0 * d0 + c1 * d1, pd1 = c2 * d0 + c3 * d1;
        if (nt < 4) { psA0 += ps0; psA1 += ps1; pdA0 += pd0; pdA1 += pd1; }
        else        { psB0 += ps0; psB1 += ps1; pdB0 += pd0; pdB1 += pd1; }
    }
    // reduce over tid4 quad (xor 1, 2 stay within the quad)
    #pragma unroll
    for (int o = 1; o < 4; o <<= 1) {
        psA0 += __shfl_xor_sync(0xffffffffu, psA0, o);
        psA1 += __shfl_xor_sync(0xffffffffu, psA1, o);
        psB0 += __shfl_xor_sync(0xffffffffu, psB0, o);
        psB1 += __shfl_xor_sync(0xffffffffu, psB1, o);
        pdA0 += __shfl_xor_sync(0xffffffffu, pdA0, o);
        pdA1 += __shfl_xor_sync(0xffffffffu, pdA1, o);
        pdB0 += __shfl_xor_sync(0xffffffffu, pdB0, o);
        pdB1 += __shfl_xor_sync(0xffffffffu, pdB1, o);
    }
    if (tid4 == 0) {
        int hA = nhalf * 2;
        if (row0 < n) {
            als[row0 * 4 + hA] = psA0;
            als[row0 * 4 + hA + 1] = psB0;
            ald[row0 * 4 + hA] = pdA0;
            ald[row0 * 4 + hA + 1] = pdB0;
        }
        if (row1 < n) {
            als[row1 * 4 + hA] = psA1;
            als[row1 * 4 + hA + 1] = psB1;
            ald[row1 * 4 + hA] = pdA1;
            ald[row1 * 4 + hA + 1] = pdB1;
        }
    }
}

// ---------------- GEMM 128->32 (fp16 A in, packed f32x2) -> fp16 H + logits --------
__global__ __launch_bounds__(256) void gemm32_kernel(
    const uint2* __restrict__ Ah, const float* __restrict__ W,
    const float* __restrict__ asrc, const float* __restrict__ adst,
    __half* __restrict__ Hh, float* __restrict__ als, float* __restrict__ ald, int n)
{
    __shared__ unsigned long long Wp[64 * 32];
    __shared__ float4 Asm4[2048];
    int tid = threadIdx.x;
    #pragma unroll 2
    for (int i = tid; i < 2048; i += 256) {
        int k2 = i >> 5, l = i & 31;
        Wp[i] = packf2(W[(k2 * 2) * 32 + l], W[(k2 * 2 + 1) * 32 + l]);
    }
    int rowbase = blockIdx.x * 64;
    #pragma unroll 2
    for (int i = tid; i < 2048; i += 256) {
        int row = rowbase + (i >> 5);
        float4 a = make_float4(0.f, 0.f, 0.f, 0.f);
        if (row < n) {
            uint2 p = Ah[(size_t)row * 32 + (i & 31)];
            float2 lo = __half22float2(*(__half2*)&p.x);
            float2 hi = __half22float2(*(__half2*)&p.y);
            a = make_float4(lo.x, lo.y, hi.x, hi.y);
        }
        Asm4[i] = a;
    }
    __syncthreads();

    int w = tid >> 5, lane = tid & 31;
    unsigned long long acc[8];
    #pragma unroll
    for (int r = 0; r < 8; r++) acc[r] = 0ull;

    #pragma unroll 4
    for (int k4 = 0; k4 < 32; k4++) {
        unsigned long long w0 = Wp[(2 * k4) * 32 + lane];
        unsigned long long w1 = Wp[(2 * k4 + 1) * 32 + lane];
        #pragma unroll
        for (int r = 0; r < 8; r++) {
            ulonglong2 ap = *(const ulonglong2*)&Asm4[(w * 8 + r) * 32 + k4];
            FMA2(acc[r], ap.x, w0);
            FMA2(acc[r], ap.y, w1);
        }
    }

    float asl = asrc[lane], adl = adst[lane];
    #pragma unroll
    for (int r = 0; r < 8; r++) {
        int row = rowbase + w * 8 + r;
        if (row >= n) break;
        float v = f2lo(acc[r]) + f2hi(acc[r]);
        Hh[(size_t)row * 32 + lane] = __float2half_rn(v);
        float ps = v * asl;
        float pd = v * adl;
        #pragma unroll
        for (int o = 1; o < 32; o <<= 1) {
            ps += __shfl_xor_sync(0xffffffffu, ps, o);
            pd += __shfl_xor_sync(0xffffffffu, pd, o);
        }
        if (lane == 0) { als[row] = ps; ald[row] = pd; }
    }
}

// ---------------- aggregation 4 heads x 32ch, fp16 H gathers -> fp16 feat ----------
__global__ __launch_bounds__(256) void agg128_kernel(
    const uint2* __restrict__ Hh, const float* __restrict__ als,
    const float* __restrict__ ald,
    const float* __restrict__ bias, const float* __restrict__ gamma,
    const float* __restrict__ beta, const float* __restrict__ mean,
    const float* __restrict__ var,
    uint2* __restrict__ out2, int n)
{
    int v = (blockIdx.x * blockDim.x + threadIdx.x) >> 5;
    if (v >= n) return;
    int lane = threadIdx.x & 31;
    int head = lane >> 3;
    float aldv = __ldg(&ald[v * 4 + head]);
    int s0 = g_off[v], s1 = g_off[v + 1];
    float s = 0.f;
    float4 acc = make_float4(0.f, 0.f, 0.f, 0.f);

    int idx = s0;
    for (; idx + 4 <= s1; idx += 4) {
        int u0 = __ldg(&g_csr[idx]);
        int u1 = __ldg(&g_csr[idx + 1]);
        int u2 = __ldg(&g_csr[idx + 2]);
        int u3 = __ldg(&g_csr[idx + 3]);
        float e0 = __ldg(&als[u0 * 4 + head]) + aldv;
        float e1 = __ldg(&als[u1 * 4 + head]) + aldv;
        float e2 = __ldg(&als[u2 * 4 + head]) + aldv;
        float e3 = __ldg(&als[u3 * 4 + head]) + aldv;
        uint2 p0 = __ldg(&Hh[(size_t)u0 * 32 + lane]);
        uint2 p1 = __ldg(&Hh[(size_t)u1 * 32 + lane]);
        uint2 p2 = __ldg(&Hh[(size_t)u2 * 32 + lane]);
        uint2 p3 = __ldg(&Hh[(size_t)u3 * 32 + lane]);
        float w0 = __expf(lrelu(e0));
        float w1 = __expf(lrelu(e1));
        float w2 = __expf(lrelu(e2));
        float w3 = __expf(lrelu(e3));
        s += (w0 + w1) + (w2 + w3);
        float2 a0 = __half22float2(*(__half2*)&p0.x), b0 = __half22float2(*(__half2*)&p0.y);
        float2 a1 = __half22float2(*(__half2*)&p1.x), b1 = __half22float2(*(__half2*)&p1.y);
        float2 a2 = __half22float2(*(__half2*)&p2.x), b2 = __half22float2(*(__half2*)&p2.y);
        float2 a3 = __half22float2(*(__half2*)&p3.x), b3 = __half22float2(*(__half2*)&p3.y);
        acc.x += w0 * a0.x + w1 * a1.x + w2 * a2.x + w3 * a3.x;
        acc.y += w0 * a0.y + w1 * a1.y + w2 * a2.y + w3 * a3.y;
        acc.z += w0 * b0.x + w1 * b1.x + w2 * b2.x + w3 * b3.x;
        acc.w += w0 * b0.y + w1 * b1.y + w2 * b2.y + w3 * b3.y;
    }
    for (; idx < s1; idx++) {
        int u = __ldg(&g_csr[idx]);
        float wt = __expf(lrelu(__ldg(&als[u * 4 + head]) + aldv));
        uint2 p = __ldg(&Hh[(size_t)u * 32 + lane]);
        float2 a = __half22float2(*(__half2*)&p.x), b = __half22float2(*(__half2*)&p.y);
        s += wt;
        acc.x += wt * a.x;
        acc.y += wt * a.y;
        acc.z += wt * b.x;
        acc.w += wt * b.y;
    }

    float inv = 1.f / (s + 1e-16f);
    float4 bi = ((const float4*)bias)[lane];
    float4 mn = ((const float4*)mean)[lane];
    float4 vr = ((const float4*)var)[lane];
    float4 gm = ((const float4*)gamma)[lane];
    float4 bt = ((const float4*)beta)[lane];
    float4 y;
    y.x = (acc.x * inv + bi.x - mn.x) * rsqrtf(vr.x + 1e-5f) * gm.x + bt.x;
    y.y = (acc.y * inv + bi.y - mn.y) * rsqrtf(vr.y + 1e-5f) * gm.y + bt.y;
    y.z = (acc.z * inv + bi.z - mn.z) * rsqrtf(vr.z + 1e-5f) * gm.z + bt.z;
    y.w = (acc.w * inv + bi.w - mn.w) * rsqrtf(vr.w + 1e-5f) * gm.w + bt.w;
    y.x = y.x > 0.f ? y.x : expm1f(y.x);
    y.y = y.y > 0.f ? y.y : expm1f(y.y);
    y.z = y.z > 0.f ? y.z : expm1f(y.z);
    y.w = y.w > 0.f ? y.w : expm1f(y.w);
    uint2 o;
    *(__half2*)&o.x = __floats2half2_rn(y.x, y.y);
    *(__half2*)&o.y = __floats2half2_rn(y.z, y.w);
    out2[(size_t)v * 32 + lane] = o;
}

// ---------------- layer-2 aggregation (fp16 H) + BN + ELU + classifier --------------
__global__ __launch_bounds__(256) void agg32_kernel(
    const __half* __restrict__ H, const float* __restrict__ als,
    const float* __restrict__ ald,
    const float* __restrict__ bias, const float* __restrict__ gamma,
    const float* __restrict__ beta, const float* __restrict__ mean,
    const float* __restrict__ var,
    const float* __restrict__ Wc, const float* __restrict__ bc,
    float* __restrict__ out, int n)
{
    int v = (blockIdx.x * blockDim.x + threadIdx.x) >> 5;
    if (v >= n) return;
    int lane = threadIdx.x & 31;
    float aldv = __ldg(&ald[v]);
    int s0 = g_off[v], s1 = g_off[v + 1];
    float s = 0.f, acc = 0.f;

    int idx = s0;
    for (; idx + 4 <= s1; idx += 4) {
        int u0 = __ldg(&g_csr[idx]);
        int u1 = __ldg(&g_csr[idx + 1]);
        int u2 = __ldg(&g_csr[idx + 2]);
        int u3 = __ldg(&g_csr[idx + 3]);
        float e0 = __ldg(&als[u0]) + aldv;
        float e1 = __ldg(&als[u1]) + aldv;
        float e2 = __ldg(&als[u2]) + aldv;
        float e3 = __ldg(&als[u3]) + aldv;
        float h0 = __half2float(__ldg(&H[(size_t)u0 * 32 + lane]));
        float h1 = __half2float(__ldg(&H[(size_t)u1 * 32 + lane]));
        float h2 = __half2float(__ldg(&H[(size_t)u2 * 32 + lane]));
        float h3 = __half2float(__ldg(&H[(size_t)u3 * 32 + lane]));
        float w0 = __expf(lrelu(e0));
        float w1 = __expf(lrelu(e1));
        float w2 = __expf(lrelu(e2));
        float w3 = __expf(lrelu(e3));
        s += (w0 + w1) + (w2 + w3);
        acc += w0 * h0 + w1 * h1 + w2 * h2 + w3 * h3;
    }
    for (; idx < s1; idx++) {
        int u = __ldg(&g_csr[idx]);
        float wt = __expf(lrelu(__ldg(&als[u]) + aldv));
        s += wt;
        acc += wt * __half2float(__ldg(&H[(size_t)u * 32 + lane]));
    }

    float y = acc / (s + 1e-16f) + bias[lane];
    y = (y - mean[lane]) * rsqrtf(var[lane] + 1e-5f) * gamma[lane] + beta[lane];
    y = y > 0.f ? y : expm1f(y);
    #pragma unroll
    for (int cc = 0; cc < 10; cc++) {
        float p = y * Wc[lane * 10 + cc];
        #pragma unroll
        for (int o = 16; o; o >>= 1) p += __shfl_xor_sync(0xffffffffu, p, o);
        if (lane == 0) out[(size_t)v * 10 + cc] = p + bc[cc];
    }
}

// ---------------- launch ----------------
extern "C" void kernel_launch(void* const* d_in, const int* in_sizes, int n_in,
                              void* d_out, int out_size) {
    const float* x   = (const float*)d_in[0];
    const int*   ei  = (const int*)d_in[1];
    const float* W0  = (const float*)d_in[2];
    const float* as0 = (const float*)d_in[3];
    const float* ad0 = (const float*)d_in[4];
    const float* b0  = (const float*)d_in[5];
    const float* gm0 = (const float*)d_in[6];
    const float* bt0 = (const float*)d_in[7];
    const float* m0  = (const float*)d_in[8];
    const float* v0  = (const float*)d_in[9];
    const float* W1  = (const float*)d_in[10];
    const float* as1 = (const float*)d_in[11];
    const float* ad1 = (const float*)d_in[12];
    const float* b1  = (const float*)d_in[13];
    const float* gm1 = (const float*)d_in[14];
    const float* bt1 = (const float*)d_in[15];
    const float* m1  = (const float*)d_in[16];
    const float* v1  = (const float*)d_in[17];
    const float* W2  = (const float*)d_in[18];
    const float* as2 = (const float*)d_in[19];
    const float* ad2 = (const float*)d_in[20];
    const float* b2  = (const float*)d_in[21];
    const float* gm2 = (const float*)d_in[22];
    const float* bt2 = (const float*)d_in[23];
    const float* m2  = (const float*)d_in[24];
    const float* v2  = (const float*)d_in[25];
    const float* Wc  = (const float*)d_in[26];
    const float* bc  = (const float*)d_in[27];

    int n = in_sizes[0] / 128;   // 100000
    int e = in_sizes[1] / 2;     // 1600000

    __half *feat, *hh, *h2;
    float *als, *ald;
    uint2 *wfh0, *wfl0, *wfh1, *wfl1;
    cudaGetSymbolAddress((void**)&feat, g_feat);
    cudaGetSymbolAddress((void**)&hh, g_hh);
    cudaGetSymbolAddress((void**)&h2, g_h2);
    cudaGetSymbolAddress((void**)&als, g_als);
    cudaGetSymbolAddress((void**)&ald, g_ald);
    cudaGetSymbolAddress((void**)&wfh0, g_WfH0);
    cudaGetSymbolAddress((void**)&wfl0, g_WfL0);
    cudaGetSymbolAddress((void**)&wfh1, g_WfH1);
    cudaGetSymbolAddress((void**)&wfl1, g_WfL1);

    // side stream + fork/join events (created once; host-side resources only)
    static cudaStream_t s2 = nullptr;
    static cudaEvent_t evFork = nullptr, evCsr = nullptr;
    if (!s2) {
        cudaStreamCreateWithFlags(&s2, cudaStreamNonBlocking);
        cudaEventCreateWithFlags(&evFork, cudaEventDisableTiming);
        cudaEventCreateWithFlags(&evCsr, cudaEventDisableTiming);
    }

    int nb = (n + 1023) / 1024;
    int eb = (e + 255) / 256;
    int g128_blocks = (n + 63) / 64;
    int g32_blocks = (n + 63) / 64;
    int agg_blocks = (n + 7) / 8;

    // fork: CSR build on s2, overlapped with W prepack + layer-0 GEMM on main stream
    cudaEventRecord(evFork, 0);
    cudaStreamWaitEvent(s2, evFork, 0);

    zero_deg_kernel<<<(n + 255) / 256, 256, 0, s2>>>(n);
    count_kernel<<<eb, 256, 0, s2>>>(ei, e);
    scan1_kernel<<<nb, 1024, 0, s2>>>(n);
    scan2_kernel<<<1, 128, 0, s2>>>(nb);
    scan3_kernel<<<nb, 1024, 0, s2>>>(n, e);
    fill_kernel<<<eb, 256, 0, s2>>>(ei, e);
    cudaEventRecord(evCsr, s2);

    // main stream: prepack W0/W1 fragments, then layer-0 GEMM (fp32 input)
    packWfrag_kernel<<<16, 256>>>(W0, wfh0, wfl0);
    packWfrag_kernel<<<16, 256>>>(W1, wfh1, wfl1);
    gemm128_mma_kernel<0><<<g128_blocks, 256>>>(
        x, wfh0, wfl0, as0, ad0, (__half2*)hh, als, ald, n);

    // join: aggregation needs both the GEMM and the CSR
    cudaStreamWaitEvent(0, evCsr, 0);

    // layer 0 aggregation -> fp16 feat
    agg128_kernel<<<agg_blocks, 256>>>(
        (const uint2*)hh, als, ald, b0, gm0, bt0, m0, v0, (uint2*)feat, n);

    // layer 1 (fp16 input)
    gemm128_mma_kernel<1><<<g128_blocks, 256>>>(
        feat, wfh1, wfl1, as1, ad1, (__half2*)hh, als, ald, n);
    agg128_kernel<<<agg_blocks, 256>>>(
        (const uint2*)hh, als, ald, b1, gm1, bt1, m1, v1, (uint2*)feat, n);

    // layer 2 (single head, fp16 in/out) + classifier
    gemm32_kernel<<<g32_blocks, 256>>>(
        (const uint2*)feat, W2, as2, ad2, h2, als, ald, n);
    agg32_kernel<<<agg_blocks, 256>>>(
        h2, als, ald, b2, gm2, bt2, m2, v2, Wc, bc, (float*)d_out, n);
}

// round 14
// speedup vs baseline: 1.3737x; 1.0409x over previous
#include <cuda_runtime.h>
#include <cuda_fp16.h>
#include <cuda_bf16.h>
#include <math.h>
#include <stdint.h>

#define NNODES 100000
#define NEDGES 1600000

__device__ __forceinline__ float lrelu(float x) {
    return x > 0.f ? x : 0.2f * x;
}
__device__ __forceinline__ uint32_t packbf2(__nv_bfloat16 a, __nv_bfloat16 b) {
    return (uint32_t)__bfloat16_as_ushort(a) | ((uint32_t)__bfloat16_as_ushort(b) << 16);
}

// bf16 tensor-core mma: m16n8k16, fp32 accumulate (base sm_80 feature)
__device__ __forceinline__ void mma_bf16(float* c, uint32_t a0, uint32_t a1,
                                         uint32_t a2, uint32_t a3,
                                         uint32_t b0, uint32_t b1) {
    asm volatile(
        "mma.sync.aligned.m16n8k16.row.col.f32.bf16.bf16.f32 "
        "{%0,%1,%2,%3}, {%4,%5,%6,%7}, {%8,%9}, {%0,%1,%2,%3};"
        : "+f"(c[0]), "+f"(c[1]), "+f"(c[2]), "+f"(c[3])
        : "r"(a0), "r"(a1), "r"(a2), "r"(a3), "r"(b0), "r"(b1));
}

// ---------------- scratch (device globals) ----------------
__device__ __align__(128) __half g_feat[NNODES * 128];  // fp16 aggregated features
__device__ __align__(128) __half g_hh[NNODES * 128];    // fp16 H for layers 0/1
__device__ __align__(128) __half g_h2[NNODES * 32];     // fp16 H for layer 2
__device__ __align__(128) uint2 g_WfH0[4096];
__device__ __align__(128) uint2 g_WfL0[4096];
__device__ __align__(128) uint2 g_WfH1[4096];
__device__ __align__(128) uint2 g_WfL1[4096];
__device__ __align__(128) uint2 g_WfH2[1024];
__device__ __align__(128) uint2 g_WfL2[1024];
__device__ float g_als[NNODES * 4];
__device__ float g_ald[NNODES * 4];
__device__ int   g_deg[NNODES];
__device__ int   g_off[NNODES + 1];
__device__ int   g_cur[NNODES];
__device__ int   g_bsum[128];
__device__ int   g_csr[NEDGES];

// ---------------- CSR build ----------------
__global__ void count_kernel(const int* __restrict__ ei, int e) {
    int i = blockIdx.x * blockDim.x + threadIdx.x;
    if (i < e) atomicAdd(&g_deg[ei[e + i]], 1);
}
__global__ void scan1_kernel(int n) {
    __shared__ int sm[1024];
    int i = blockIdx.x * 1024 + threadIdx.x;
    int v = (i < n) ? g_deg[i] : 0;
    sm[threadIdx.x] = v;
    __syncthreads();
    #pragma unroll
    for (int d = 1; d < 1024; d <<= 1) {
        int t = (threadIdx.x >= d) ? sm[threadIdx.x - d] : 0;
        __syncthreads();
        sm[threadIdx.x] += t;
        __syncthreads();
    }
    if (i < n) g_off[i] = sm[threadIdx.x] - v;   // exclusive within block
    if (threadIdx.x == 1023) g_bsum[blockIdx.x] = sm[1023];
}
// scan3 with folded block-sum prefix (replaces scan2+scan3)
__global__ void scan3_kernel(int n, int e, int nb) {
    __shared__ int off;
    int t = threadIdx.x;
    if (t == 0) {
        int run = 0;
        int lim = blockIdx.x < nb ? blockIdx.x : nb;
        for (int j = 0; j < lim; j++) run += g_bsum[j];
        off = run;
    }
    __syncthreads();
    int i = blockIdx.x * 1024 + t;
    if (i < n) {
        int o = g_off[i] + off;
        g_off[i] = o;
        g_cur[i] = o;
    }
    if (i == 0) g_off[n] = e;
}
__global__ void fill_kernel(const int* __restrict__ ei, int e) {
    int i = blockIdx.x * blockDim.x + threadIdx.x;
    if (i < e) {
        int src = ei[i];
        int dst = ei[e + i];
        int pos = atomicAdd(&g_cur[dst], 1);
        g_csr[pos] = src;
    }
}

// ---------------- W fragment prepack (all three weights, one launch) ---------------
// frag layout: tile = kt*(ncols/8) + nt; lane: tid4=lane&3, grp=lane>>2;
// n = nt*8+grp, k0 = kt*16+tid4*2;
// reg0 = {W[k0][n], W[k0+1][n]}, reg1 = {W[k0+8][n], W[k0+9][n]}.
__device__ __forceinline__ void pack_one(const float* W, int ncols, int i,
                                         uint2* wfh, uint2* wfl) {
    int lane = i & 31, tile = i >> 5;
    int ntiles = ncols >> 3;
    int kt = tile / ntiles, nt = tile - kt * ntiles;
    int tid4 = lane & 3, grp = lane >> 2;
    int n = nt * 8 + grp;
    int k0 = kt * 16 + tid4 * 2;
    float w00 = W[k0 * ncols + n];
    float w01 = W[(k0 + 1) * ncols + n];
    float w08 = W[(k0 + 8) * ncols + n];
    float w09 = W[(k0 + 9) * ncols + n];
    __nv_bfloat16 h00 = __float2bfloat16_rn(w00);
    __nv_bfloat16 h01 = __float2bfloat16_rn(w01);
    __nv_bfloat16 h08 = __float2bfloat16_rn(w08);
    __nv_bfloat16 h09 = __float2bfloat16_rn(w09);
    uint2 ph, pl;
    ph.x = packbf2(h00, h01);
    ph.y = packbf2(h08, h09);
    pl.x = packbf2(__float2bfloat16_rn(w00 - __bfloat162float(h00)),
                   __float2bfloat16_rn(w01 - __bfloat162float(h01)));
    pl.y = packbf2(__float2bfloat16_rn(w08 - __bfloat162float(h08)),
                   __float2bfloat16_rn(w09 - __bfloat162float(h09)));
    wfh[i] = ph;
    wfl[i] = pl;
}
__global__ void packAll_kernel(const float* __restrict__ W0,
                               const float* __restrict__ W1,
                               const float* __restrict__ W2) {
    int b = blockIdx.x;
    int tid = threadIdx.x;
    if (b < 16)       pack_one(W0, 128, b * 256 + tid, g_WfH0, g_WfL0);
    else if (b < 32)  pack_one(W1, 128, (b - 16) * 256 + tid, g_WfH1, g_WfL1);
    else              pack_one(W2, 32, (b - 32) * 256 + tid, g_WfH2, g_WfL2);
}

// ---------------- GEMM 128->128 via bf16 tensor cores (3-pass hi/lo) ---------------
#define ASTRIDE 136
template <int HALFIN>
__global__ __launch_bounds__(256) void gemm128_mma_kernel(
    const void* __restrict__ Ain,
    const uint2* __restrict__ wfh, const uint2* __restrict__ wfl,
    const float* __restrict__ asrc, const float* __restrict__ adst,
    __half2* __restrict__ Hh, float* __restrict__ als, float* __restrict__ ald, int n)
{
    __shared__ __nv_bfloat16 Ahi[64 * ASTRIDE];
    __shared__ __nv_bfloat16 Alo[64 * ASTRIDE];
    int tid = threadIdx.x;
    int rowbase = blockIdx.x * 64;

    for (int i = tid; i < 8192; i += 256) {
        int r = i >> 7, c = i & 127;
        int row = rowbase + r;
        float a = 0.f;
        if (row < n) {
            if (HALFIN) a = __half2float(((const __half*)Ain)[(size_t)row * 128 + c]);
            else        a = ((const float*)Ain)[(size_t)row * 128 + c];
        }
        __nv_bfloat16 h = __float2bfloat16_rn(a);
        Ahi[r * ASTRIDE + c] = h;
        Alo[r * ASTRIDE + c] = __float2bfloat16_rn(a - __bfloat162float(h));
    }
    __syncthreads();

    int w = tid >> 5, lane = tid & 31;
    int mt = w & 3, nhalf = w >> 2;
    int tid4 = lane & 3, grp = lane >> 2;
    int mbase = mt * 16;

    float acc[8][4];
    #pragma unroll
    for (int t = 0; t < 8; t++)
        #pragma unroll
        for (int c = 0; c < 4; c++) acc[t][c] = 0.f;

    const uint32_t* Ah32 = (const uint32_t*)Ahi;
    const uint32_t* Al32 = (const uint32_t*)Alo;
    int ra = (mbase + grp) * ASTRIDE;
    int rb = (mbase + grp + 8) * ASTRIDE;

    #pragma unroll
    for (int kt = 0; kt < 8; kt++) {
        int k0 = kt * 16 + tid4 * 2;
        uint32_t ah0 = Ah32[(ra + k0) >> 1];
        uint32_t ah1 = Ah32[(rb + k0) >> 1];
        uint32_t ah2 = Ah32[(ra + k0 + 8) >> 1];
        uint32_t ah3 = Ah32[(rb + k0 + 8) >> 1];
        uint32_t al0 = Al32[(ra + k0) >> 1];
        uint32_t al1 = Al32[(rb + k0) >> 1];
        uint32_t al2 = Al32[(ra + k0 + 8) >> 1];
        uint32_t al3 = Al32[(rb + k0 + 8) >> 1];
        #pragma unroll
        for (int nt = 0; nt < 8; nt++) {
            int tile = kt * 16 + nhalf * 8 + nt;
            uint2 bh = __ldg(&wfh[tile * 32 + lane]);
            uint2 bl = __ldg(&wfl[tile * 32 + lane]);
            mma_bf16(acc[nt], ah0, ah1, ah2, ah3, bh.x, bh.y);
            mma_bf16(acc[nt], ah0, ah1, ah2, ah3, bl.x, bl.y);
            mma_bf16(acc[nt], al0, al1, al2, al3, bh.x, bh.y);
        }
    }

    int row0 = rowbase + mbase + grp;
    int row1 = row0 + 8;
    float psA0 = 0.f, psA1 = 0.f, psB0 = 0.f, psB1 = 0.f;
    float pdA0 = 0.f, pdA1 = 0.f, pdB0 = 0.f, pdB1 = 0.f;
    #pragma unroll
    for (int nt = 0; nt < 8; nt++) {
        int cb = nhalf * 64 + nt * 8 + tid4 * 2;
        float c0 = acc[nt][0], c1 = acc[nt][1], c2 = acc[nt][2], c3 = acc[nt][3];
        if (row0 < n) Hh[(size_t)row0 * 64 + (cb >> 1)] = __floats2half2_rn(c0, c1);
        if (row1 < n) Hh[(size_t)row1 * 64 + (cb >> 1)] = __floats2half2_rn(c2, c3);
        float s0 = asrc[cb], s1 = asrc[cb + 1];
        float d0 = adst[cb], d1 = adst[cb + 1];
        float ps0 = c0 * s0 + c1 * s1, ps1 = c2 * s0 + c3 * s1;
        float pd0 = c0 * d0 + c1 * d1, pd1 = c2 * d0 + c3 * d1;
        if (nt < 4) { psA0 += ps0; psA1 += ps1; pdA0 += pd0; pdA1 += pd1; }
        else        { psB0 += ps0; psB1 += ps1; pdB0 += pd0; pdB1 += pd1; }
    }
    #pragma unroll
    for (int o = 1; o < 4; o <<= 1) {
        psA0 += __shfl_xor_sync(0xffffffffu, psA0, o);
        psA1 += __shfl_xor_sync(0xffffffffu, psA1, o);
        psB0 += __shfl_xor_sync(0xffffffffu, psB0, o);
        psB1 += __shfl_xor_sync(0xffffffffu, psB1, o);
        pdA0 += __shfl_xor_sync(0xffffffffu, pdA0, o);
        pdA1 += __shfl_xor_sync(0xffffffffu, pdA1, o);
        pdB0 += __shfl_xor_sync(0xffffffffu, pdB0, o);
        pdB1 += __shfl_xor_sync(0xffffffffu, pdB1, o);
    }
    if (tid4 == 0) {
        int hA = nhalf * 2;
        if (row0 < n) {
            als[row0 * 4 + hA] = psA0;
            als[row0 * 4 + hA + 1] = psB0;
            ald[row0 * 4 + hA] = pdA0;
            ald[row0 * 4 + hA + 1] = pdB0;
        }
        if (row1 < n) {
            als[row1 * 4 + hA] = psA1;
            als[row1 * 4 + hA + 1] = psB1;
            ald[row1 * 4 + hA] = pdA1;
            ald[row1 * 4 + hA + 1] = pdB1;
        }
    }
}

// ---------------- GEMM 128->32 via bf16 tensor cores (fp16 A, 1 head) --------------
// CTA = 128 rows, 8 warps; warp w owns rows w*16..+15, all 32 cols (4 ntiles).
__global__ __launch_bounds__(256) void gemm32_mma_kernel(
    const __half* __restrict__ Ah,
    const uint2* __restrict__ wfh, const uint2* __restrict__ wfl,
    const float* __restrict__ asrc, const float* __restrict__ adst,
    __half2* __restrict__ Hh, float* __restrict__ als, float* __restrict__ ald, int n)
{
    extern __shared__ __nv_bfloat16 smA[];
    __nv_bfloat16* Ahi = smA;                    // 128*ASTRIDE
    __nv_bfloat16* Alo = smA + 128 * ASTRIDE;
    int tid = threadIdx.x;
    int rowbase = blockIdx.x * 128;

    for (int i = tid; i < 16384; i += 256) {
        int r = i >> 7, c = i & 127;
        int row = rowbase + r;
        float a = (row < n) ? __half2float(Ah[(size_t)row * 128 + c]) : 0.f;
        __nv_bfloat16 h = __float2bfloat16_rn(a);
        Ahi[r * ASTRIDE + c] = h;
        Alo[r * ASTRIDE + c] = __float2bfloat16_rn(a - __bfloat162float(h));
    }
    __syncthreads();

    int w = tid >> 5, lane = tid & 31;
    int tid4 = lane & 3, grp = lane >> 2;
    int mbase = w * 16;

    float acc[4][4];
    #pragma unroll
    for (int t = 0; t < 4; t++)
        #pragma unroll
        for (int c = 0; c < 4; c++) acc[t][c] = 0.f;

    const uint32_t* Ah32 = (const uint32_t*)Ahi;
    const uint32_t* Al32 = (const uint32_t*)Alo;
    int ra = (mbase + grp) * ASTRIDE;
    int rb = (mbase + grp + 8) * ASTRIDE;

    #pragma unroll
    for (int kt = 0; kt < 8; kt++) {
        int k0 = kt * 16 + tid4 * 2;
        uint32_t ah0 = Ah32[(ra + k0) >> 1];
        uint32_t ah1 = Ah32[(rb + k0) >> 1];
        uint32_t ah2 = Ah32[(ra + k0 + 8) >> 1];
        uint32_t ah3 = Ah32[(rb + k0 + 8) >> 1];
        uint32_t al0 = Al32[(ra + k0) >> 1];
        uint32_t al1 = Al32[(rb + k0) >> 1];
        uint32_t al2 = Al32[(ra + k0 + 8) >> 1];
        uint32_t al3 = Al32[(rb + k0 + 8) >> 1];
        #pragma unroll
        for (int nt = 0; nt < 4; nt++) {
            int tile = kt * 4 + nt;
            uint2 bh = __ldg(&wfh[tile * 32 + lane]);
            uint2 bl = __ldg(&wfl[tile * 32 + lane]);
            mma_bf16(acc[nt], ah0, ah1, ah2, ah3, bh.x, bh.y);
            mma_bf16(acc[nt], ah0, ah1, ah2, ah3, bl.x, bl.y);
            mma_bf16(acc[nt], al0, al1, al2, al3, bh.x, bh.y);
        }
    }

    int row0 = rowbase + mbase + grp;
    int row1 = row0 + 8;
    float ps0 = 0.f, ps1 = 0.f, pd0 = 0.f, pd1 = 0.f;
    #pragma unroll
    for (int nt = 0; nt < 4; nt++) {
        int cb = nt * 8 + tid4 * 2;
        float c0 = acc[nt][0], c1 = acc[nt][1], c2 = acc[nt][2], c3 = acc[nt][3];
        if (row0 < n) Hh[(size_t)row0 * 16 + (cb >> 1)] = __floats2half2_rn(c0, c1);
        if (row1 < n) Hh[(size_t)row1 * 16 + (cb >> 1)] = __floats2half2_rn(c2, c3);
        float s0 = asrc[cb], s1 = asrc[cb + 1];
        float d0 = adst[cb], d1 = adst[cb + 1];
        ps0 += c0 * s0 + c1 * s1;
        ps1 += c2 * s0 + c3 * s1;
        pd0 += c0 * d0 + c1 * d1;
        pd1 += c2 * d0 + c3 * d1;
    }
    #pragma unroll
    for (int o = 1; o < 4; o <<= 1) {
        ps0 += __shfl_xor_sync(0xffffffffu, ps0, o);
        ps1 += __shfl_xor_sync(0xffffffffu, ps1, o);
        pd0 += __shfl_xor_sync(0xffffffffu, pd0, o);
        pd1 += __shfl_xor_sync(0xffffffffu, pd1, o);
    }
    if (tid4 == 0) {
        if (row0 < n) { als[row0] = ps0; ald[row0] = pd0; }
        if (row1 < n) { als[row1] = ps1; ald[row1] = pd1; }
    }
}

// ---------------- aggregation 4 heads x 32ch, fp16 H gathers -> fp16 feat ----------
__global__ __launch_bounds__(256) void agg128_kernel(
    const uint2* __restrict__ Hh, const float* __restrict__ als,
    const float* __restrict__ ald,
    const float* __restrict__ bias, const float* __restrict__ gamma,
    const float* __restrict__ beta, const float* __restrict__ mean,
    const float* __restrict__ var,
    uint2* __restrict__ out2, int n)
{
    int v = (blockIdx.x * blockDim.x + threadIdx.x) >> 5;
    if (v >= n) return;
    int lane = threadIdx.x & 31;
    int head = lane >> 3;
    float aldv = __ldg(&ald[v * 4 + head]);
    int s0 = g_off[v], s1 = g_off[v + 1];
    float s = 0.f;
    float4 acc = make_float4(0.f, 0.f, 0.f, 0.f);

    int idx = s0;
    for (; idx + 4 <= s1; idx += 4) {
        int u0 = __ldg(&g_csr[idx]);
        int u1 = __ldg(&g_csr[idx + 1]);
        int u2 = __ldg(&g_csr[idx + 2]);
        int u3 = __ldg(&g_csr[idx + 3]);
        float e0 = __ldg(&als[u0 * 4 + head]) + aldv;
        float e1 = __ldg(&als[u1 * 4 + head]) + aldv;
        float e2 = __ldg(&als[u2 * 4 + head]) + aldv;
        float e3 = __ldg(&als[u3 * 4 + head]) + aldv;
        uint2 p0 = __ldg(&Hh[(size_t)u0 * 32 + lane]);
        uint2 p1 = __ldg(&Hh[(size_t)u1 * 32 + lane]);
        uint2 p2 = __ldg(&Hh[(size_t)u2 * 32 + lane]);
        uint2 p3 = __ldg(&Hh[(size_t)u3 * 32 + lane]);
        float w0 = __expf(lrelu(e0));
        float w1 = __expf(lrelu(e1));
        float w2 = __expf(lrelu(e2));
        float w3 = __expf(lrelu(e3));
        s += (w0 + w1) + (w2 + w3);
        float2 a0 = __half22float2(*(__half2*)&p0.x), b0 = __half22float2(*(__half2*)&p0.y);
        float2 a1 = __half22float2(*(__half2*)&p1.x), b1 = __half22float2(*(__half2*)&p1.y);
        float2 a2 = __half22float2(*(__half2*)&p2.x), b2 = __half22float2(*(__half2*)&p2.y);
        float2 a3 = __half22float2(*(__half2*)&p3.x), b3 = __half22float2(*(__half2*)&p3.y);
        acc.x += w0 * a0.x + w1 * a1.x + w2 * a2.x + w3 * a3.x;
        acc.y += w0 * a0.y + w1 * a1.y + w2 * a2.y + w3 * a3.y;
        acc.z += w0 * b0.x + w1 * b1.x + w2 * b2.x + w3 * b3.x;
        acc.w += w0 * b0.y + w1 * b1.y + w2 * b2.y + w3 * b3.y;
    }
    for (; idx < s1; idx++) {
        int u = __ldg(&g_csr[idx]);
        float wt = __expf(lrelu(__ldg(&als[u * 4 + head]) + aldv));
        uint2 p = __ldg(&Hh[(size_t)u * 32 + lane]);
        float2 a = __half22float2(*(__half2*)&p.x), b = __half22float2(*(__half2*)&p.y);
        s += wt;
        acc.x += wt * a.x;
        acc.y += wt * a.y;
        acc.z += wt * b.x;
        acc.w += wt * b.y;
    }

    float inv = 1.f / (s + 1e-16f);
    float4 bi = ((const float4*)bias)[lane];
    float4 mn = ((const float4*)mean)[lane];
    float4 vr = ((const float4*)var)[lane];
    float4 gm = ((const float4*)gamma)[lane];
    float4 bt = ((const float4*)beta)[lane];
    float4 y;
    y.x = (acc.x * inv + bi.x - mn.x) * rsqrtf(vr.x + 1e-5f) * gm.x + bt.x;
    y.y = (acc.y * inv + bi.y - mn.y) * rsqrtf(vr.y + 1e-5f) * gm.y + bt.y;
    y.z = (acc.z * inv + bi.z - mn.z) * rsqrtf(vr.z + 1e-5f) * gm.z + bt.z;
    y.w = (acc.w * inv + bi.w - mn.w) * rsqrtf(vr.w + 1e-5f) * gm.w + bt.w;
    y.x = y.x > 0.f ? y.x : expm1f(y.x);
    y.y = y.y > 0.f ? y.y : expm1f(y.y);
    y.z = y.z > 0.f ? y.z : expm1f(y.z);
    y.w = y.w > 0.f ? y.w : expm1f(y.w);
    uint2 o;
    *(__half2*)&o.x = __floats2half2_rn(y.x, y.y);
    *(__half2*)&o.y = __floats2half2_rn(y.z, y.w);
    out2[(size_t)v * 32 + lane] = o;
}

// ---------------- layer-2 aggregation (fp16 H) + BN + ELU + classifier --------------
__global__ __launch_bounds__(256) void agg32_kernel(
    const __half* __restrict__ H, const float* __restrict__ als,
    const float* __restrict__ ald,
    const float* __restrict__ bias, const float* __restrict__ gamma,
    const float* __restrict__ beta, const float* __restrict__ mean,
    const float* __restrict__ var,
    const float* __restrict__ Wc, const float* __restrict__ bc,
    float* __restrict__ out, int n)
{
    int v = (blockIdx.x * blockDim.x + threadIdx.x) >> 5;
    if (v >= n) return;
    int lane = threadIdx.x & 31;
    float aldv = __ldg(&ald[v]);
    int s0 = g_off[v], s1 = g_off[v + 1];
    float s = 0.f, acc = 0.f;

    int idx = s0;
    for (; idx + 4 <= s1; idx += 4) {
        int u0 = __ldg(&g_csr[idx]);
        int u1 = __ldg(&g_csr[idx + 1]);
        int u2 = __ldg(&g_csr[idx + 2]);
        int u3 = __ldg(&g_csr[idx + 3]);
        float e0 = __ldg(&als[u0]) + aldv;
        float e1 = __ldg(&als[u1]) + aldv;
        float e2 = __ldg(&als[u2]) + aldv;
        float e3 = __ldg(&als[u3]) + aldv;
        float h0 = __half2float(__ldg(&H[(size_t)u0 * 32 + lane]));
        float h1 = __half2float(__ldg(&H[(size_t)u1 * 32 + lane]));
        float h2 = __half2float(__ldg(&H[(size_t)u2 * 32 + lane]));
        float h3 = __half2float(__ldg(&H[(size_t)u3 * 32 + lane]));
        float w0 = __expf(lrelu(e0));
        float w1 = __expf(lrelu(e1));
        float w2 = __expf(lrelu(e2));
        float w3 = __expf(lrelu(e3));
        s += (w0 + w1) + (w2 + w3);
        acc += w0 * h0 + w1 * h1 + w2 * h2 + w3 * h3;
    }
    for (; idx < s1; idx++) {
        int u = __ldg(&g_csr[idx]);
        float wt = __expf(lrelu(__ldg(&als[u]) + aldv));
        s += wt;
        acc += wt * __half2float(__ldg(&H[(size_t)u * 32 + lane]));
    }

    float y = acc / (s + 1e-16f) + bias[lane];
    y = (y - mean[lane]) * rsqrtf(var[lane] + 1e-5f) * gamma[lane] + beta[lane];
    y = y > 0.f ? y : expm1f(y);
    #pragma unroll
    for (int cc = 0; cc < 10; cc++) {
        float p = y * Wc[lane * 10 + cc];
        #pragma unroll
        for (int o = 16; o; o >>= 1) p += __shfl_xor_sync(0xffffffffu, p, o);
        if (lane == 0) out[(size_t)v * 10 + cc] = p + bc[cc];
    }
}

// ---------------- launch ----------------
extern "C" void kernel_launch(void* const* d_in, const int* in_sizes, int n_in,
                              void* d_out, int out_size) {
    const float* x   = (const float*)d_in[0];
    const int*   ei  = (const int*)d_in[1];
    const float* W0  = (const float*)d_in[2];
    const float* as0 = (const float*)d_in[3];
    const float* ad0 = (const float*)d_in[4];
    const float* b0  = (const float*)d_in[5];
    const float* gm0 = (const float*)d_in[6];
    const float* bt0 = (const float*)d_in[7];
    const float* m0  = (const float*)d_in[8];
    const float* v0  = (const float*)d_in[9];
    const float* W1  = (const float*)d_in[10];
    const float* as1 = (const float*)d_in[11];
    const float* ad1 = (const float*)d_in[12];
    const float* b1  = (const float*)d_in[13];
    const float* gm1 = (const float*)d_in[14];
    const float* bt1 = (const float*)d_in[15];
    const float* m1  = (const float*)d_in[16];
    const float* v1  = (const float*)d_in[17];
    const float* W2  = (const float*)d_in[18];
    const float* as2 = (const float*)d_in[19];
    const float* ad2 = (const float*)d_in[20];
    const float* b2  = (const float*)d_in[21];
    const float* gm2 = (const float*)d_in[22];
    const float* bt2 = (const float*)d_in[23];
    const float* m2  = (const float*)d_in[24];
    const float* v2  = (const float*)d_in[25];
    const float* Wc  = (const float*)d_in[26];
    const float* bc  = (const float*)d_in[27];

    int n = in_sizes[0] / 128;   // 100000
    int e = in_sizes[1] / 2;     // 1600000

    __half *feat, *hh, *h2;
    float *als, *ald;
    int *deg;
    uint2 *wfh0, *wfl0, *wfh1, *wfl1, *wfh2, *wfl2;
    cudaGetSymbolAddress((void**)&feat, g_feat);
    cudaGetSymbolAddress((void**)&hh, g_hh);
    cudaGetSymbolAddress((void**)&h2, g_h2);
    cudaGetSymbolAddress((void**)&als, g_als);
    cudaGetSymbolAddress((void**)&ald, g_ald);
    cudaGetSymbolAddress((void**)&deg, g_deg);
    cudaGetSymbolAddress((void**)&wfh0, g_WfH0);
    cudaGetSymbolAddress((void**)&wfl0, g_WfL0);
    cudaGetSymbolAddress((void**)&wfh1, g_WfH1);
    cudaGetSymbolAddress((void**)&wfl1, g_WfL1);
    cudaGetSymbolAddress((void**)&wfh2, g_WfH2);
    cudaGetSymbolAddress((void**)&wfl2, g_WfL2);

    // side stream + fork/join events (created once; host-side resources only)
    static cudaStream_t s2 = nullptr;
    static cudaEvent_t evFork = nullptr, evCsr = nullptr;
    static bool attrSet = false;
    if (!s2) {
        cudaStreamCreateWithFlags(&s2, cudaStreamNonBlocking);
        cudaEventCreateWithFlags(&evFork, cudaEventDisableTiming);
        cudaEventCreateWithFlags(&evCsr, cudaEventDisableTiming);
    }
    if (!attrSet) {
        cudaFuncSetAttribute(gemm32_mma_kernel,
                             cudaFuncAttributeMaxDynamicSharedMemorySize,
                             2 * 128 * ASTRIDE * 2);
        attrSet = true;
    }

    int nb = (n + 1023) / 1024;
    int eb = (e + 255) / 256;
    int g128_blocks = (n + 63) / 64;
    int g32_blocks = (n + 127) / 128;
    int agg_blocks = (n + 7) / 8;

    // fork: CSR build on s2, overlapped with W prepack + layer-0 GEMM on main stream
    cudaEventRecord(evFork, 0);
    cudaStreamWaitEvent(s2, evFork, 0);

    cudaMemsetAsync(deg, 0, (size_t)n * sizeof(int), s2);
    count_kernel<<<eb, 256, 0, s2>>>(ei, e);
    scan1_kernel<<<nb, 1024, 0, s2>>>(n);
    scan3_kernel<<<nb, 1024, 0, s2>>>(n, e, nb);
    fill_kernel<<<eb, 256, 0, s2>>>(ei, e);
    cudaEventRecord(evCsr, s2);

    // main stream: prepack all W fragments (one launch), layer-0 GEMM (fp32 input)
    packAll_kernel<<<36, 256>>>(W0, W1, W2);
    gemm128_mma_kernel<0><<<g128_blocks, 256>>>(
        x, wfh0, wfl0, as0, ad0, (__half2*)hh, als, ald, n);

    // join: aggregation needs both the GEMM and the CSR
    cudaStreamWaitEvent(0, evCsr, 0);

    // layer 0 aggregation -> fp16 feat
    agg128_kernel<<<agg_blocks, 256>>>(
        (const uint2*)hh, als, ald, b0, gm0, bt0, m0, v0, (uint2*)feat, n);

    // layer 1 (fp16 input)
    gemm128_mma_kernel<1><<<g128_blocks, 256>>>(
        feat, wfh1, wfl1, as1, ad1, (__half2*)hh, als, ald, n);
    agg128_kernel<<<agg_blocks, 256>>>(
        (const uint2*)hh, als, ald, b1, gm1, bt1, m1, v1, (uint2*)feat, n);

    // layer 2 (single head, tensor-core GEMM) + classifier
    gemm32_mma_kernel<<<g32_blocks, 256, 2 * 128 * ASTRIDE * 2>>>(
        feat, wfh2, wfl2, as2, ad2, (__half2*)h2, als, ald, n);
    agg32_kernel<<<agg_blocks, 256>>>(
        h2, als, ald, b2, gm2, bt2, m2, v2, Wc, bc, (float*)d_out, n);
}